// round 1
// baseline (speedup 1.0000x reference)
#include <cuda_runtime.h>
#include <math.h>

// ---------------- problem constants ----------------
constexpr int B    = 2;
constexpr int CIN  = 192;
constexpr int CMID = 180;
constexpr int Hh   = 96;
constexpr int Ww   = 96;
constexpr int HW   = Hh * Ww;          // 9216
constexpr int KK   = 9;                // 3x3 taps
constexpr int G    = 10;               // offset groups (180 / (2*9))
constexpr int CG   = CMID / G;         // 18 channels per group
constexpr int KDIM = CMID * KK;        // 1620

// ---------------- device scratch (static, allocation-free) ----------------
__device__ float g_xr  [(size_t)B * CMID * HW];        // reduced features
__device__ float g_offs[(size_t)B * 2 * CMID * HW];    // offset maps (360 ch)
__device__ float g_col [(size_t)B * KDIM * HW];        // im2col buffer (reused)
__device__ float g_fw  [(size_t)B * CMID * HW];
__device__ float g_fh  [(size_t)B * CMID * HW];
__device__ float g_avg [B * CMID];
__device__ float g_attn[B * 2];

// ---------------- generic fp32 tiled GEMM: C[b][m][n] = A[m][k]*Bm[b][k][n] + bias[m] ----------------
constexpr int BM = 64, BN = 128, BK = 16;

__global__ void __launch_bounds__(256)
gemm_bias_kernel(const float* __restrict__ A, const float* __restrict__ Bmat,
                 const float* __restrict__ bias, float* __restrict__ C,
                 int M, int N, int Kd)
{
    __shared__ float As[BK][BM + 4];
    __shared__ float Bs[BK][BN + 4];
    const int bz = blockIdx.z;
    const float* Bp = Bmat + (size_t)bz * Kd * N;
    float* Cp = C + (size_t)bz * M * N;

    const int tid = threadIdx.x;
    const int txc = tid & 15;   // 16 col groups * 8 cols
    const int tyr = tid >> 4;   // 16 row groups * 4 rows
    const int rowBase = blockIdx.y * BM;
    const int colBase = blockIdx.x * BN;

    float acc[4][8];
#pragma unroll
    for (int i = 0; i < 4; i++)
#pragma unroll
        for (int j = 0; j < 8; j++) acc[i][j] = 0.f;

    for (int k0 = 0; k0 < Kd; k0 += BK) {
#pragma unroll
        for (int l = 0; l < 4; l++) {       // A tile 64x16
            int idx = tid + l * 256;
            int m = idx >> 4, kk = idx & 15;
            int gm = rowBase + m, gk = k0 + kk;
            As[kk][m] = (gm < M && gk < Kd) ? A[(size_t)gm * Kd + gk] : 0.f;
        }
#pragma unroll
        for (int l = 0; l < 8; l++) {       // B tile 16x128
            int idx = tid + l * 256;
            int kk = idx >> 7, n = idx & 127;
            int gk = k0 + kk;
            Bs[kk][n] = (gk < Kd) ? Bp[(size_t)gk * N + colBase + n] : 0.f;
        }
        __syncthreads();
#pragma unroll
        for (int kk = 0; kk < BK; kk++) {
            float a[4], bb[8];
#pragma unroll
            for (int i = 0; i < 4; i++) a[i] = As[kk][tyr * 4 + i];
#pragma unroll
            for (int j = 0; j < 8; j++) bb[j] = Bs[kk][txc * 8 + j];
#pragma unroll
            for (int i = 0; i < 4; i++)
#pragma unroll
                for (int j = 0; j < 8; j++) acc[i][j] += a[i] * bb[j];
        }
        __syncthreads();
    }
#pragma unroll
    for (int i = 0; i < 4; i++) {
        int gm = rowBase + tyr * 4 + i;
        if (gm < M) {
            float bv = bias[gm];
#pragma unroll
            for (int j = 0; j < 8; j++)
                Cp[(size_t)gm * N + colBase + txc * 8 + j] = acc[i][j] + bv;
        }
    }
}

// GEMM where B matrix is built on the fly as a0*fh + a1*fw (attn mix fused)
__global__ void __launch_bounds__(256)
gemm_mix_bias_kernel(const float* __restrict__ A,
                     const float* __restrict__ fh, const float* __restrict__ fw,
                     const float* __restrict__ attn,
                     const float* __restrict__ bias, float* __restrict__ C,
                     int M, int N, int Kd)
{
    __shared__ float As[BK][BM + 4];
    __shared__ float Bs[BK][BN + 4];
    const int bz = blockIdx.z;
    const float* Bh = fh + (size_t)bz * Kd * N;
    const float* Bw = fw + (size_t)bz * Kd * N;
    const float a0 = attn[bz * 2 + 0];   // multiplies f_h
    const float a1 = attn[bz * 2 + 1];   // multiplies f_w
    float* Cp = C + (size_t)bz * M * N;

    const int tid = threadIdx.x;
    const int txc = tid & 15;
    const int tyr = tid >> 4;
    const int rowBase = blockIdx.y * BM;
    const int colBase = blockIdx.x * BN;

    float acc[4][8];
#pragma unroll
    for (int i = 0; i < 4; i++)
#pragma unroll
        for (int j = 0; j < 8; j++) acc[i][j] = 0.f;

    for (int k0 = 0; k0 < Kd; k0 += BK) {
#pragma unroll
        for (int l = 0; l < 4; l++) {
            int idx = tid + l * 256;
            int m = idx >> 4, kk = idx & 15;
            int gm = rowBase + m, gk = k0 + kk;
            As[kk][m] = (gm < M && gk < Kd) ? A[(size_t)gm * Kd + gk] : 0.f;
        }
#pragma unroll
        for (int l = 0; l < 8; l++) {
            int idx = tid + l * 256;
            int kk = idx >> 7, n = idx & 127;
            int gk = k0 + kk;
            size_t off = (size_t)gk * N + colBase + n;
            Bs[kk][n] = (gk < Kd) ? (a0 * Bh[off] + a1 * Bw[off]) : 0.f;
        }
        __syncthreads();
#pragma unroll
        for (int kk = 0; kk < BK; kk++) {
            float a[4], bb[8];
#pragma unroll
            for (int i = 0; i < 4; i++) a[i] = As[kk][tyr * 4 + i];
#pragma unroll
            for (int j = 0; j < 8; j++) bb[j] = Bs[kk][txc * 8 + j];
#pragma unroll
            for (int i = 0; i < 4; i++)
#pragma unroll
                for (int j = 0; j < 8; j++) acc[i][j] += a[i] * bb[j];
        }
        __syncthreads();
    }
#pragma unroll
    for (int i = 0; i < 4; i++) {
        int gm = rowBase + tyr * 4 + i;
        if (gm < M) {
            float bv = bias[gm];
#pragma unroll
            for (int j = 0; j < 8; j++)
                Cp[(size_t)gm * N + colBase + txc * 8 + j] = acc[i][j] + bv;
        }
    }
}

// ---------------- deformable im2col ----------------
// col[b][k=(g*CG+c)*KK + kk][p] = bilinear(xr[b][g*CG+c], tap kk at pixel p, offsets)
__global__ void __launch_bounds__(256)
im2col_deform_kernel(const float* __restrict__ xr, const float* __restrict__ offs,
                     int coff, float* __restrict__ col)
{
    const int b = blockIdx.z;
    const int g = blockIdx.y;
    const int p = blockIdx.x * blockDim.x + threadIdx.x;
    if (p >= HW) return;
    const int h = p / Ww, w = p % Ww;

    const float* xb   = xr   + (size_t)b * CMID * HW + (size_t)(g * CG) * HW;
    const float* offb = offs + (size_t)b * (2 * CMID) * HW + (size_t)coff * HW;
    float* colb = col + (size_t)b * KDIM * HW;

#pragma unroll
    for (int kk = 0; kk < KK; kk++) {
        float oy = offb[(size_t)(g * 18 + kk * 2 + 0) * HW + p];
        float ox = offb[(size_t)(g * 18 + kk * 2 + 1) * HW + p];
        float sy = oy + (float)(kk / 3 - 1 + h);
        float sx = ox + (float)(kk % 3 - 1 + w);
        float y0f = floorf(sy), x0f = floorf(sx);
        float dy = sy - y0f, dx = sx - x0f;
        int y0 = (int)y0f, x0 = (int)x0f;
        int y1 = y0 + 1, x1 = x0 + 1;
        bool vy0 = (y0 >= 0) & (y0 < Hh);
        bool vy1 = (y1 >= 0) & (y1 < Hh);
        bool vx0 = (x0 >= 0) & (x0 < Ww);
        bool vx1 = (x1 >= 0) & (x1 < Ww);
        int y0c = min(max(y0, 0), Hh - 1);
        int y1c = min(max(y1, 0), Hh - 1);
        int x0c = min(max(x0, 0), Ww - 1);
        int x1c = min(max(x1, 0), Ww - 1);
        float w00 = (1.f - dy) * (1.f - dx) * (float)(vy0 && vx0);
        float w01 = (1.f - dy) * dx        * (float)(vy0 && vx1);
        float w10 = dy * (1.f - dx)        * (float)(vy1 && vx0);
        float w11 = dy * dx                * (float)(vy1 && vx1);
        int i00 = y0c * Ww + x0c, i01 = y0c * Ww + x1c;
        int i10 = y1c * Ww + x0c, i11 = y1c * Ww + x1c;

        float* colp = colb + ((size_t)(g * CG) * KK + kk) * HW + p;
#pragma unroll
        for (int c = 0; c < CG; c++) {
            const float* xc = xb + (size_t)c * HW;
            float v = w00 * xc[i00] + w01 * xc[i01] + w10 * xc[i10] + w11 * xc[i11];
            colp[(size_t)c * KK * HW] = v;
        }
    }
}

// ---------------- mean over HW of (fw+fh) per (b,c) ----------------
__global__ void reduce_mean_kernel(const float* __restrict__ fw,
                                   const float* __restrict__ fh,
                                   float* __restrict__ avg)
{
    const int bc = blockIdx.x;   // 0 .. B*CMID-1
    const float* a = fw + (size_t)bc * HW;
    const float* b = fh + (size_t)bc * HW;
    float s = 0.f;
    for (int i = threadIdx.x; i < HW; i += 256) s += a[i] + b[i];
    __shared__ float sm[256];
    sm[threadIdx.x] = s;
    __syncthreads();
    for (int st = 128; st > 0; st >>= 1) {
        if (threadIdx.x < st) sm[threadIdx.x] += sm[threadIdx.x + st];
        __syncthreads();
    }
    if (threadIdx.x == 0) avg[bc] = sm[0] * (1.0f / HW);
}

// ---------------- attention softmax over 2 logits per batch ----------------
__global__ void attn_kernel(const float* __restrict__ avg,
                            const float* __restrict__ w_attn,
                            const float* __restrict__ b_attn,
                            float* __restrict__ attn)
{
    const int t = threadIdx.x;
    __shared__ float logits[4];
    if (t < 4) {
        int b = t >> 1, o = t & 1;
        float s = b_attn[o];
        for (int c = 0; c < CMID; c++)
            s += avg[b * CMID + c] * w_attn[o * CMID + c];
        logits[t] = s;
    }
    __syncthreads();
    if (t < 2) {
        float l0 = logits[t * 2 + 0], l1 = logits[t * 2 + 1];
        float m = fmaxf(l0, l1);
        float e0 = expf(l0 - m), e1 = expf(l1 - m);
        float inv = 1.f / (e0 + e1);
        attn[t * 2 + 0] = e0 * inv;   // weight for f_h
        attn[t * 2 + 1] = e1 * inv;   // weight for f_w
    }
}

// ---------------- launcher ----------------
extern "C" void kernel_launch(void* const* d_in, const int* in_sizes, int n_in,
                              void* d_out, int out_size)
{
    const float* x        = (const float*)d_in[0];
    const float* w_reduce = (const float*)d_in[1];
    const float* b_reduce = (const float*)d_in[2];
    const float* w_offset = (const float*)d_in[3];
    const float* b_offset = (const float*)d_in[4];
    const float* w_dcnw   = (const float*)d_in[5];
    const float* b_dcnw   = (const float*)d_in[6];
    const float* w_dcnh   = (const float*)d_in[7];
    const float* b_dcnh   = (const float*)d_in[8];
    const float* w_expand = (const float*)d_in[9];
    const float* b_expand = (const float*)d_in[10];
    const float* w_attn   = (const float*)d_in[11];
    const float* b_attn   = (const float*)d_in[12];
    float* out = (float*)d_out;

    float *xr, *offs, *col, *fw, *fh, *avg, *attn;
    cudaGetSymbolAddress((void**)&xr,   g_xr);
    cudaGetSymbolAddress((void**)&offs, g_offs);
    cudaGetSymbolAddress((void**)&col,  g_col);
    cudaGetSymbolAddress((void**)&fw,   g_fw);
    cudaGetSymbolAddress((void**)&fh,   g_fh);
    cudaGetSymbolAddress((void**)&avg,  g_avg);
    cudaGetSymbolAddress((void**)&attn, g_attn);

    const dim3 blk(256);
    const int gx = HW / BN;   // 72

    // 1) xr = reduce(x)
    gemm_bias_kernel<<<dim3(gx, (CMID + BM - 1) / BM, B), blk>>>(
        w_reduce, x, b_reduce, xr, CMID, HW, CIN);

    // 2) offs = offset(xr)
    gemm_bias_kernel<<<dim3(gx, (2 * CMID + BM - 1) / BM, B), blk>>>(
        w_offset, xr, b_offset, offs, 2 * CMID, HW, CMID);

    // 3) f_w path: im2col with off_w (channels [0,180)) + GEMM
    im2col_deform_kernel<<<dim3(HW / 256, G, B), blk>>>(xr, offs, 0, col);
    gemm_bias_kernel<<<dim3(gx, (CMID + BM - 1) / BM, B), blk>>>(
        w_dcnw, col, b_dcnw, fw, CMID, HW, KDIM);

    // 4) f_h path: im2col with off_h (channels [180,360)) + GEMM (col reused)
    im2col_deform_kernel<<<dim3(HW / 256, G, B), blk>>>(xr, offs, CMID, col);
    gemm_bias_kernel<<<dim3(gx, (CMID + BM - 1) / BM, B), blk>>>(
        w_dcnh, col, b_dcnh, fh, CMID, HW, KDIM);

    // 5) global average + attention
    reduce_mean_kernel<<<B * CMID, blk>>>(fw, fh, avg);
    attn_kernel<<<1, 64>>>(avg, w_attn, b_attn, attn);

    // 6) out = expand(attn0*f_h + attn1*f_w)
    gemm_mix_bias_kernel<<<dim3(gx, (CIN + BM - 1) / BM, B), blk>>>(
        w_expand, fh, fw, attn, b_expand, out, CIN, HW, CMID);
}

// round 2
// speedup vs baseline: 1.6049x; 1.6049x over previous
#include <cuda_runtime.h>
#include <math.h>

// ---------------- problem constants ----------------
constexpr int B    = 2;
constexpr int CIN  = 192;
constexpr int CMID = 180;
constexpr int Hh   = 96;
constexpr int Ww   = 96;
constexpr int HW   = Hh * Ww;          // 9216
constexpr int KK   = 9;                // 3x3 taps
constexpr int G    = 10;               // offset groups
constexpr int CG   = CMID / G;         // 18 channels per group
constexpr int KDIM = CMID * KK;        // 1620

// padded K sizes (multiples of 16) so GEMM B-tile loads are unguarded
constexpr int CMID_P = 192;            // 180 -> 192
constexpr int KDIM_P = 1632;           // 1620 -> 1632

// per-batch strides
constexpr size_t XRS  = (size_t)CMID_P * HW;     // xr / fw / fh (padded rows zero)
constexpr size_t OFS  = (size_t)2 * CMID * HW;   // offs
constexpr size_t COLS_ = (size_t)KDIM_P * HW;    // col buffers (padded rows zero)

// ---------------- device scratch (zero-initialized; pad rows never written) --
__device__ float g_xr  [(size_t)B * XRS];
__device__ float g_offs[(size_t)B * OFS];
__device__ float g_colw[(size_t)B * COLS_];
__device__ float g_colh[(size_t)B * COLS_];
__device__ float g_fw  [(size_t)B * XRS];
__device__ float g_fh  [(size_t)B * XRS];
__device__ float g_avg [B * CMID];
__device__ float g_attn[B * 2];

// ---------------- packed f32x2 helpers ----------------
typedef unsigned long long u64;

__device__ __forceinline__ u64 fma2(u64 a, u64 b, u64 c) {
    u64 d;
    asm("fma.rn.f32x2 %0, %1, %2, %3;" : "=l"(d) : "l"(a), "l"(b), "l"(c));
    return d;
}
__device__ __forceinline__ float2 u2f(u64 v) {
    float2 f;
    asm("mov.b64 {%0, %1}, %2;" : "=f"(f.x), "=f"(f.y) : "l"(v));
    return f;
}

// ---------------- FFMA2 GEMM: C[z][m][n] = sum_k A[m][k]*B[z][k][n] + bias[m]
constexpr int BM = 64, BN = 128, BK = 16;

// shared tile load/store helpers (inlined via macros for both gemm variants)
#define GEMM_BODY(LOAD_B_EXPR)                                                   \
    __shared__ __align__(16) float2 As[2][BK][BM + 2];                           \
    __shared__ __align__(16) float  Bs[2][BK][BN];                               \
    const int tid = threadIdx.x;                                                 \
    const int tx  = tid & 15, ty = tid >> 4;                                     \
    const int rowBase = blockIdx.y * BM, colBase = blockIdx.x * BN;              \
    const int m_l = tid & 63;                                                    \
    const int kb  = (tid >> 6) * 8;                                              \
    const int gmA = rowBase + m_l;                                               \
    const int nk  = (Kd + BK - 1) / BK;                                          \
    u64 acc[8][4];                                                               \
    _Pragma("unroll") for (int i = 0; i < 8; i++)                                \
        _Pragma("unroll") for (int j = 0; j < 4; j++) acc[i][j] = 0ull;          \
    float  aR[8];                                                                \
    float4 bR[4];                                                                \
    /* prologue: tile 0 */                                                       \
    _Pragma("unroll") for (int q = 0; q < 8; q++) {                              \
        int gk = kb + q;                                                         \
        aR[q] = (gmA < M && gk < Kd) ? A[(size_t)gmA * Kd + gk] : 0.f;           \
    }                                                                            \
    _Pragma("unroll") for (int r = 0; r < 4; r++) {                              \
        int lin = tid + r * 128; int row = lin >> 5, cv = lin & 31;              \
        int k0 = 0; LOAD_B_EXPR;                                                 \
    }                                                                            \
    _Pragma("unroll") for (int q = 0; q < 8; q++)                                \
        As[0][kb + q][m_l] = make_float2(aR[q], aR[q]);                          \
    _Pragma("unroll") for (int r = 0; r < 4; r++) {                              \
        int lin = tid + r * 128; int row = lin >> 5, cv = lin & 31;              \
        *reinterpret_cast<float4*>(&Bs[0][row][cv * 4]) = bR[r];                 \
    }                                                                            \
    __syncthreads();                                                             \
    for (int t = 0; t < nk; ++t) {                                               \
        const int s = t & 1;                                                     \
        if (t + 1 < nk) {                                                        \
            const int k0 = (t + 1) * BK;                                         \
            _Pragma("unroll") for (int q = 0; q < 8; q++) {                      \
                int gk = k0 + kb + q;                                            \
                aR[q] = (gmA < M && gk < Kd) ? A[(size_t)gmA * Kd + gk] : 0.f;   \
            }                                                                    \
            _Pragma("unroll") for (int r = 0; r < 4; r++) {                      \
                int lin = tid + r * 128; int row = lin >> 5, cv = lin & 31;      \
                LOAD_B_EXPR;                                                     \
            }                                                                    \
        }                                                                        \
        _Pragma("unroll") for (int kk = 0; kk < BK; kk++) {                      \
            const ulonglong2* ap =                                               \
                reinterpret_cast<const ulonglong2*>(&As[s][kk][ty * 8]);         \
            ulonglong2 av0 = ap[0], av1 = ap[1], av2 = ap[2], av3 = ap[3];       \
            u64 a2[8] = {av0.x, av0.y, av1.x, av1.y, av2.x, av2.y, av3.x, av3.y};\
            const ulonglong2* bp =                                               \
                reinterpret_cast<const ulonglong2*>(&Bs[s][kk][tx * 8]);         \
            ulonglong2 bv0 = bp[0], bv1 = bp[1];                                 \
            u64 b2[4] = {bv0.x, bv0.y, bv1.x, bv1.y};                            \
            _Pragma("unroll") for (int i = 0; i < 8; i++)                        \
                _Pragma("unroll") for (int j = 0; j < 4; j++)                    \
                    acc[i][j] = fma2(a2[i], b2[j], acc[i][j]);                   \
        }                                                                        \
        if (t + 1 < nk) {                                                        \
            const int sn = s ^ 1;                                                \
            _Pragma("unroll") for (int q = 0; q < 8; q++)                        \
                As[sn][kb + q][m_l] = make_float2(aR[q], aR[q]);                 \
            _Pragma("unroll") for (int r = 0; r < 4; r++) {                      \
                int lin = tid + r * 128; int row = lin >> 5, cv = lin & 31;      \
                *reinterpret_cast<float4*>(&Bs[sn][row][cv * 4]) = bR[r];        \
            }                                                                    \
            __syncthreads();                                                     \
        }                                                                        \
    }                                                                            \
    _Pragma("unroll") for (int i = 0; i < 8; i++) {                              \
        int gm = rowBase + ty * 8 + i;                                           \
        if (gm < M) {                                                            \
            float bv = bias[gm];                                                 \
            float2 p0 = u2f(acc[i][0]), p1 = u2f(acc[i][1]);                     \
            float2 p2 = u2f(acc[i][2]), p3 = u2f(acc[i][3]);                     \
            float4 c0 = make_float4(p0.x + bv, p0.y + bv, p1.x + bv, p1.y + bv); \
            float4 c1 = make_float4(p2.x + bv, p2.y + bv, p3.x + bv, p3.y + bv); \
            float4* o = reinterpret_cast<float4*>(                               \
                &Cp[(size_t)gm * N + colBase + tx * 8]);                         \
            o[0] = c0; o[1] = c1;                                                \
        }                                                                        \
    }

__global__ void __launch_bounds__(128)
gemm_bias_kernel(const float* __restrict__ A, const float* __restrict__ Bm,
                 const float* __restrict__ bias, float* __restrict__ C,
                 int M, int N, int Kd, size_t sB, size_t sC)
{
    const float* Bp = Bm + (size_t)blockIdx.z * sB;
    float* Cp = C + (size_t)blockIdx.z * sC;
    GEMM_BODY(
        bR[r] = *reinterpret_cast<const float4*>(
            &Bp[(size_t)(k0 + row) * N + colBase + cv * 4]);
    )
}

// GEMM with B = a0*fh + a1*fw built on the fly (attention mix fused)
__global__ void __launch_bounds__(128)
gemm_mix_bias_kernel(const float* __restrict__ A,
                     const float* __restrict__ fh, const float* __restrict__ fw,
                     const float* __restrict__ attn,
                     const float* __restrict__ bias, float* __restrict__ C,
                     int M, int N, int Kd, size_t sB, size_t sC)
{
    const float* Bh = fh + (size_t)blockIdx.z * sB;
    const float* Bw = fw + (size_t)blockIdx.z * sB;
    const float a0 = attn[blockIdx.z * 2 + 0];
    const float a1 = attn[blockIdx.z * 2 + 1];
    float* Cp = C + (size_t)blockIdx.z * sC;
    GEMM_BODY(
        {
            size_t off = (size_t)(k0 + row) * N + colBase + cv * 4;
            float4 vh = *reinterpret_cast<const float4*>(&Bh[off]);
            float4 vw = *reinterpret_cast<const float4*>(&Bw[off]);
            bR[r] = make_float4(a0 * vh.x + a1 * vw.x, a0 * vh.y + a1 * vw.y,
                                a0 * vh.z + a1 * vw.z, a0 * vh.w + a1 * vw.w);
        }
    )
}

// ---------------- deformable im2col (both convs fused) ----------------
__global__ void __launch_bounds__(256)
im2col_deform_kernel(const float* __restrict__ xr, const float* __restrict__ offs,
                     float* __restrict__ colw, float* __restrict__ colh)
{
    const int b = blockIdx.z;
    const int g = blockIdx.y;
    const int p = blockIdx.x * blockDim.x + threadIdx.x;
    if (p >= HW) return;
    const int h = p / Ww, w = p % Ww;

    const float* xb = xr + (size_t)b * XRS + (size_t)(g * CG) * HW;

#pragma unroll
    for (int conv = 0; conv < 2; conv++) {
        const float* offb = offs + (size_t)b * OFS + (size_t)(conv ? CMID : 0) * HW;
        float* colb = (conv ? colh : colw) + (size_t)b * COLS_
                      + (size_t)(g * CG) * KK * HW + p;

#pragma unroll
        for (int kk = 0; kk < KK; kk++) {
            float oy = offb[(size_t)(g * 18 + kk * 2 + 0) * HW + p];
            float ox = offb[(size_t)(g * 18 + kk * 2 + 1) * HW + p];
            float sy = oy + (float)(kk / 3 - 1 + h);
            float sx = ox + (float)(kk % 3 - 1 + w);
            float y0f = floorf(sy), x0f = floorf(sx);
            float dy = sy - y0f, dx = sx - x0f;
            int y0 = (int)y0f, x0 = (int)x0f;
            int y1 = y0 + 1, x1 = x0 + 1;
            bool vy0 = (y0 >= 0) & (y0 < Hh);
            bool vy1 = (y1 >= 0) & (y1 < Hh);
            bool vx0 = (x0 >= 0) & (x0 < Ww);
            bool vx1 = (x1 >= 0) & (x1 < Ww);
            int y0c = min(max(y0, 0), Hh - 1);
            int y1c = min(max(y1, 0), Hh - 1);
            int x0c = min(max(x0, 0), Ww - 1);
            int x1c = min(max(x1, 0), Ww - 1);
            float w00 = (1.f - dy) * (1.f - dx) * (float)(vy0 && vx0);
            float w01 = (1.f - dy) * dx        * (float)(vy0 && vx1);
            float w10 = dy * (1.f - dx)        * (float)(vy1 && vx0);
            float w11 = dy * dx                * (float)(vy1 && vx1);
            int i00 = y0c * Ww + x0c, i01 = y0c * Ww + x1c;
            int i10 = y1c * Ww + x0c, i11 = y1c * Ww + x1c;

#pragma unroll
            for (int c = 0; c < CG; c++) {
                const float* xc = xb + (size_t)c * HW;
                float v = w00 * xc[i00] + w01 * xc[i01]
                        + w10 * xc[i10] + w11 * xc[i11];
                colb[(size_t)(c * KK + kk) * HW] = v;
            }
        }
    }
}

// ---------------- mean over HW of (fw+fh) per (b,c) ----------------
__global__ void reduce_mean_kernel(const float* __restrict__ fw,
                                   const float* __restrict__ fh,
                                   float* __restrict__ avg)
{
    const int bc = blockIdx.x;           // 0 .. B*CMID-1
    const int bb = bc / CMID, cc = bc % CMID;
    const float* a = fw + (size_t)bb * XRS + (size_t)cc * HW;
    const float* b = fh + (size_t)bb * XRS + (size_t)cc * HW;
    float s = 0.f;
    for (int i = threadIdx.x; i < HW; i += 256) s += a[i] + b[i];
    __shared__ float sm[256];
    sm[threadIdx.x] = s;
    __syncthreads();
    for (int st = 128; st > 0; st >>= 1) {
        if (threadIdx.x < st) sm[threadIdx.x] += sm[threadIdx.x + st];
        __syncthreads();
    }
    if (threadIdx.x == 0) avg[bc] = sm[0] * (1.0f / HW);
}

// ---------------- attention softmax over 2 logits per batch ----------------
__global__ void attn_kernel(const float* __restrict__ avg,
                            const float* __restrict__ w_attn,
                            const float* __restrict__ b_attn,
                            float* __restrict__ attn)
{
    const int t = threadIdx.x;
    __shared__ float logits[4];
    if (t < 4) {
        int b = t >> 1, o = t & 1;
        float s = b_attn[o];
        for (int c = 0; c < CMID; c++)
            s += avg[b * CMID + c] * w_attn[o * CMID + c];
        logits[t] = s;
    }
    __syncthreads();
    if (t < 2) {
        float l0 = logits[t * 2 + 0], l1 = logits[t * 2 + 1];
        float m = fmaxf(l0, l1);
        float e0 = expf(l0 - m), e1 = expf(l1 - m);
        float inv = 1.f / (e0 + e1);
        attn[t * 2 + 0] = e0 * inv;     // weight for f_h
        attn[t * 2 + 1] = e1 * inv;     // weight for f_w
    }
}

// ---------------- launcher ----------------
extern "C" void kernel_launch(void* const* d_in, const int* in_sizes, int n_in,
                              void* d_out, int out_size)
{
    const float* x        = (const float*)d_in[0];
    const float* w_reduce = (const float*)d_in[1];
    const float* b_reduce = (const float*)d_in[2];
    const float* w_offset = (const float*)d_in[3];
    const float* b_offset = (const float*)d_in[4];
    const float* w_dcnw   = (const float*)d_in[5];
    const float* b_dcnw   = (const float*)d_in[6];
    const float* w_dcnh   = (const float*)d_in[7];
    const float* b_dcnh   = (const float*)d_in[8];
    const float* w_expand = (const float*)d_in[9];
    const float* b_expand = (const float*)d_in[10];
    const float* w_attn   = (const float*)d_in[11];
    const float* b_attn   = (const float*)d_in[12];
    float* out = (float*)d_out;

    float *xr, *offs, *colw, *colh, *fw, *fh, *avg, *attn;
    cudaGetSymbolAddress((void**)&xr,   g_xr);
    cudaGetSymbolAddress((void**)&offs, g_offs);
    cudaGetSymbolAddress((void**)&colw, g_colw);
    cudaGetSymbolAddress((void**)&colh, g_colh);
    cudaGetSymbolAddress((void**)&fw,   g_fw);
    cudaGetSymbolAddress((void**)&fh,   g_fh);
    cudaGetSymbolAddress((void**)&avg,  g_avg);
    cudaGetSymbolAddress((void**)&attn, g_attn);

    const dim3 blk(128);
    const int gx = HW / BN;   // 72

    // 1) xr = reduce(x)            M=180, K=192
    gemm_bias_kernel<<<dim3(gx, 3, B), blk>>>(
        w_reduce, x, b_reduce, xr, CMID, HW, CIN,
        (size_t)CIN * HW, XRS);

    // 2) offs = offset(xr)         M=360, K=180 (B rows padded to 192)
    gemm_bias_kernel<<<dim3(gx, 6, B), blk>>>(
        w_offset, xr, b_offset, offs, 2 * CMID, HW, CMID,
        XRS, OFS);

    // 3) both im2col passes fused
    im2col_deform_kernel<<<dim3(HW / 256, G, B), dim3(256)>>>(xr, offs, colw, colh);

    // 4) deform GEMMs              M=180, K=1620 (B rows padded to 1632)
    gemm_bias_kernel<<<dim3(gx, 3, B), blk>>>(
        w_dcnw, colw, b_dcnw, fw, CMID, HW, KDIM, COLS_, XRS);
    gemm_bias_kernel<<<dim3(gx, 3, B), blk>>>(
        w_dcnh, colh, b_dcnh, fh, CMID, HW, KDIM, COLS_, XRS);

    // 5) global average + attention
    reduce_mean_kernel<<<B * CMID, dim3(256)>>>(fw, fh, avg);
    attn_kernel<<<1, 64>>>(avg, w_attn, b_attn, attn);

    // 6) out = expand(attn0*f_h + attn1*f_w)   M=192, K=180
    gemm_mix_bias_kernel<<<dim3(gx, 3, B), blk>>>(
        w_expand, fh, fw, attn, b_expand, out, CIN, HW, CMID,
        XRS, (size_t)CIN * HW);
}

// round 4
// speedup vs baseline: 3.7275x; 2.3226x over previous
#include <cuda_runtime.h>
#include <cuda_bf16.h>
#include <math.h>
#include <stdint.h>

// ---------------- problem constants ----------------
constexpr int B    = 2;
constexpr int CIN  = 192;
constexpr int CMID = 180;
constexpr int Hh   = 96;
constexpr int Ww   = 96;
constexpr int HW   = Hh * Ww;          // 9216
constexpr int KK   = 9;
constexpr int G    = 10;
constexpr int CG   = CMID / G;         // 18
constexpr int KDIM = CMID * KK;        // 1620
constexpr int KDIM_P = 1664;           // 52 chunks of 32

// ---------------- device scratch (zero-initialized statics) ----------------
// f32 tensors
__device__ float g_xr  [(size_t)B * CMID * HW];
__device__ float g_offs[(size_t)B * 2 * CMID * HW];
__device__ float g_fw  [(size_t)B * CMID * HW];
__device__ float g_fh  [(size_t)B * CMID * HW];
__device__ float g_avg [B * CMID];
__device__ float g_attn[B * 2];
// bf16 hi/lo activation planes (K-pad rows stay zero forever)
__device__ __nv_bfloat16 g_xp_h [(size_t)B * 192 * HW];
__device__ __nv_bfloat16 g_xp_l [(size_t)B * 192 * HW];
__device__ __nv_bfloat16 g_xrp_h[(size_t)B * 192 * HW];
__device__ __nv_bfloat16 g_xrp_l[(size_t)B * 192 * HW];
__device__ __nv_bfloat16 g_cw_h [(size_t)B * KDIM_P * HW];
__device__ __nv_bfloat16 g_cw_l [(size_t)B * KDIM_P * HW];
__device__ __nv_bfloat16 g_ch_h [(size_t)B * KDIM_P * HW];
__device__ __nv_bfloat16 g_ch_l [(size_t)B * KDIM_P * HW];
__device__ __nv_bfloat16 g_mx_h [(size_t)B * 192 * HW];
__device__ __nv_bfloat16 g_mx_l [(size_t)B * 192 * HW];
// prepacked weights: [plane(hi,lo)][Kpad][Mpad] k-major
__device__ __nv_bfloat16 g_wpR[2 * 192  * 192];
__device__ __nv_bfloat16 g_wpO[2 * 192  * 384];
__device__ __nv_bfloat16 g_wpW[2 * 1664 * 192];
__device__ __nv_bfloat16 g_wpH[2 * 1664 * 192];
__device__ __nv_bfloat16 g_wpE[2 * 192  * 192];

// ---------------- PTX helpers (arch-generic only) ----------------
__device__ __forceinline__ uint32_t smem_to_u32(const void* p) {
    uint32_t a;
    asm("{ .reg .u64 t; cvta.to.shared.u64 t, %1; cvt.u32.u64 %0, t; }"
        : "=r"(a) : "l"(p));
    return a;
}
__device__ __forceinline__ void cp16(uint32_t dst, const void* src) {
    asm volatile("cp.async.cg.shared.global [%0], [%1], 16;" :: "r"(dst), "l"(src));
}
#define CP_COMMIT() asm volatile("cp.async.commit_group;" ::: "memory")
#define CP_WAIT(n)  asm volatile("cp.async.wait_group %0;" :: "n"(n) : "memory")

__device__ __forceinline__ void ldsm_x4_t(uint32_t* r, uint32_t addr) {
    asm volatile("ldmatrix.sync.aligned.m8n8.x4.trans.shared.b16 {%0,%1,%2,%3}, [%4];"
        : "=r"(r[0]), "=r"(r[1]), "=r"(r[2]), "=r"(r[3]) : "r"(addr));
}
__device__ __forceinline__ void mma16816(float* d, const uint32_t* a, const uint32_t* b) {
    asm volatile("mma.sync.aligned.m16n8k16.row.col.f32.bf16.bf16.f32 "
        "{%0,%1,%2,%3}, {%4,%5,%6,%7}, {%8,%9}, {%0,%1,%2,%3};"
        : "+f"(d[0]), "+f"(d[1]), "+f"(d[2]), "+f"(d[3])
        : "r"(a[0]), "r"(a[1]), "r"(a[2]), "r"(a[3]), "r"(b[0]), "r"(b[1]));
}
__device__ __forceinline__ uint32_t pack_bf16x2(__nv_bfloat16 a, __nv_bfloat16 b) {
    return (uint32_t)__bfloat16_as_ushort(a) | ((uint32_t)__bfloat16_as_ushort(b) << 16);
}
__device__ __forceinline__ void split_bf16(float v, __nv_bfloat16& h, __nv_bfloat16& l) {
    h = __float2bfloat16_rn(v);
    l = __float2bfloat16_rn(v - __bfloat162float(h));
}

// SMEM layout (bytes):
//  A: 2 bufs x (2 planes x 32 rows x 144) = 18432
//  B: 2 bufs x (2 planes x 32 rows x 272) = 34816
constexpr int SMEM_BYTES = 18432 + 34816;   // 53248

// ---------------- tensor GEMM via mma.sync (split-bf16 x3 passes) ----------
// C[z][m][p] = sum_k W[m][k] * Act[z][k][p] + bias[m]
// grid = (HW/128, Mpad/64, B), block = 256 (8 warps as 2m x 4n of 32x32 warp tiles)
template <bool PLANES>
__global__ void __launch_bounds__(256, 2)
tgemm_kernel(const __nv_bfloat16* __restrict__ bHp, const __nv_bfloat16* __restrict__ bLp,
             size_t strideBz,
             const __nv_bfloat16* __restrict__ Wp, int nChunks,
             const float* __restrict__ bias, int Mvalid,
             float* __restrict__ outF, size_t strideOz,
             __nv_bfloat16* __restrict__ outH, __nv_bfloat16* __restrict__ outL,
             size_t strideOPz)
{
    extern __shared__ char smem[];
    const uint32_t sb = smem_to_u32(smem);
    const int tid = threadIdx.x, lane = tid & 31, wid = tid >> 5;
    const int wm = wid >> 2, wn = wid & 3;
    const int z = blockIdx.z, yb = blockIdx.y;
    const int pbase = blockIdx.x * 128;
    const int Mpad = gridDim.y * 64;
    const size_t wPlane = (size_t)nChunks * 32 * Mpad;

    const __nv_bfloat16* bHz = bHp + (size_t)z * strideBz + pbase;
    const __nv_bfloat16* bLz = bLp + (size_t)z * strideBz + pbase;

    auto loadChunk = [&](int kc, int s) {
        // A: weights (both planes), 512 x 16B
#pragma unroll
        for (int i = 0; i < 2; i++) {
            int c = tid + i * 256;
            int pl = c >> 8, rem = c & 255, row = rem >> 3, cc = rem & 7;
            uint32_t dst = sb + s * 9216 + pl * 4608 + row * 144 + cc * 16;
            const __nv_bfloat16* src = Wp + (size_t)pl * wPlane
                + (size_t)(kc * 32 + row) * Mpad + yb * 64 + cc * 8;
            cp16(dst, src);
        }
        // B: activations (both planes), 1024 x 16B
#pragma unroll
        for (int i = 0; i < 4; i++) {
            int c = tid + i * 256;
            int pl = c >> 9, rem = c & 511, row = rem >> 4, cc = rem & 15;
            uint32_t dst = sb + 18432 + s * 17408 + pl * 8704 + row * 272 + cc * 16;
            const __nv_bfloat16* src = (pl ? bLz : bHz)
                + (size_t)(kc * 32 + row) * HW + cc * 8;
            cp16(dst, src);
        }
    };

    // ldmatrix per-lane addresses (A trans from [k][m], B trans from [k][n])
    const uint32_t aRow  = ((lane >> 4) & 1) * 8 + (lane & 7);
    const uint32_t aColB = (uint32_t)(wm * 32 + ((lane >> 3) & 1) * 8) * 2;
    const uint32_t bRow  = ((lane >> 3) & 1) * 8 + (lane & 7);
    const uint32_t bColB = (uint32_t)(wn * 32 + ((lane >> 4) & 1) * 8) * 2;
    uint32_t aAddr[2], bAddr[2];
    aAddr[0] = sb + aRow * 144 + aColB;          aAddr[1] = aAddr[0] + 32;   // mt*16 cols
    bAddr[0] = sb + 18432 + bRow * 272 + bColB;  bAddr[1] = bAddr[0] + 32;   // ntp*16 cols

    float acc[2][4][4];
#pragma unroll
    for (int i = 0; i < 2; i++)
#pragma unroll
        for (int j = 0; j < 4; j++)
#pragma unroll
            for (int q = 0; q < 4; q++) acc[i][j][q] = 0.f;

    loadChunk(0, 0);
    CP_COMMIT();

    for (int t = 0; t < nChunks; t++) {
        const int s = t & 1;
        if (t + 1 < nChunks) {
            loadChunk(t + 1, s ^ 1);
            CP_COMMIT();
            CP_WAIT(1);
        } else {
            CP_WAIT(0);
        }
        __syncthreads();

        const uint32_t aB = s * 9216, bB = s * 17408;
#pragma unroll
        for (int ks = 0; ks < 2; ks++) {
            uint32_t Ah[2][4], Al[2][4], Bh[2][4], Bl[2][4];
            ldsm_x4_t(Ah[0], aAddr[0] + aB + ks * 2304);
            ldsm_x4_t(Ah[1], aAddr[1] + aB + ks * 2304);
            ldsm_x4_t(Al[0], aAddr[0] + aB + 4608 + ks * 2304);
            ldsm_x4_t(Al[1], aAddr[1] + aB + 4608 + ks * 2304);
            ldsm_x4_t(Bh[0], bAddr[0] + bB + ks * 4352);
            ldsm_x4_t(Bh[1], bAddr[1] + bB + ks * 4352);
            ldsm_x4_t(Bl[0], bAddr[0] + bB + 8704 + ks * 4352);
            ldsm_x4_t(Bl[1], bAddr[1] + bB + 8704 + ks * 4352);
#pragma unroll
            for (int mt = 0; mt < 2; mt++)
#pragma unroll
                for (int nt = 0; nt < 4; nt++) {
                    const uint32_t* bh = &Bh[nt >> 1][(nt & 1) * 2];
                    const uint32_t* bl = &Bl[nt >> 1][(nt & 1) * 2];
                    mma16816(acc[mt][nt], Ah[mt], bh);   // hi*hi
                    mma16816(acc[mt][nt], Ah[mt], bl);   // hi*lo
                    mma16816(acc[mt][nt], Al[mt], bh);   // lo*hi
                }
        }
        __syncthreads();
    }

    // epilogue: scatter accumulators, add bias, optional bf16 split planes
    float* oF = outF + (size_t)z * strideOz;
    __nv_bfloat16* oH = PLANES ? (outH + (size_t)z * strideOPz) : nullptr;
    __nv_bfloat16* oL = PLANES ? (outL + (size_t)z * strideOPz) : nullptr;
#pragma unroll
    for (int mt = 0; mt < 2; mt++) {
#pragma unroll
        for (int half = 0; half < 2; half++) {
            const int m = yb * 64 + wm * 32 + mt * 16 + half * 8 + (lane >> 2);
            if (m < Mvalid) {
                const float bv = bias[m];
#pragma unroll
                for (int nt = 0; nt < 4; nt++) {
                    const int n0 = pbase + wn * 32 + nt * 8 + (lane & 3) * 2;
                    float v0 = acc[mt][nt][half * 2 + 0] + bv;
                    float v1 = acc[mt][nt][half * 2 + 1] + bv;
                    *reinterpret_cast<float2*>(&oF[(size_t)m * HW + n0]) =
                        make_float2(v0, v1);
                    if (PLANES) {
                        __nv_bfloat16 h0, l0, h1, l1;
                        split_bf16(v0, h0, l0);
                        split_bf16(v1, h1, l1);
                        *reinterpret_cast<uint32_t*>(&oH[(size_t)m * HW + n0]) =
                            pack_bf16x2(h0, h1);
                        *reinterpret_cast<uint32_t*>(&oL[(size_t)m * HW + n0]) =
                            pack_bf16x2(l0, l1);
                    }
                }
            }
        }
    }
}

// ---------------- weight prepack: [plane][Kpad][Mpad] hi/lo split -----------
__global__ void prepack_kernel(const float* __restrict__ W, int Kd, int Mvalid,
                               int Mpad, int Kpad, __nv_bfloat16* __restrict__ dst)
{
    int idx = blockIdx.x * blockDim.x + threadIdx.x;
    if (idx >= Kpad * Mpad) return;
    int k = idx / Mpad, m = idx % Mpad;
    float v = (k < Kd && m < Mvalid) ? W[(size_t)m * Kd + k] : 0.f;
    __nv_bfloat16 h, l;
    split_bf16(v, h, l);
    dst[idx] = h;
    dst[(size_t)Kpad * Mpad + idx] = l;
}

// ---------------- x -> bf16 hi/lo planes ----------------
__global__ void convert_x_kernel(const float* __restrict__ x,
                                 __nv_bfloat16* __restrict__ ph,
                                 __nv_bfloat16* __restrict__ pl, size_t n)
{
    size_t i = (size_t)blockIdx.x * blockDim.x + threadIdx.x;
    if (i >= n) return;
    __nv_bfloat16 h, l;
    split_bf16(x[i], h, l);
    ph[i] = h;
    pl[i] = l;
}

// ---------------- deformable im2col -> bf16 hi/lo col planes ----------------
__global__ void __launch_bounds__(256)
im2col_deform_kernel(const float* __restrict__ xr, const float* __restrict__ offs,
                     __nv_bfloat16* __restrict__ cwh, __nv_bfloat16* __restrict__ cwl,
                     __nv_bfloat16* __restrict__ chh, __nv_bfloat16* __restrict__ chl)
{
    const int b = blockIdx.z;
    const int g = blockIdx.y;
    const int p = blockIdx.x * blockDim.x + threadIdx.x;
    if (p >= HW) return;
    const int h = p / Ww, w = p % Ww;

    const float* xb = xr + (size_t)b * CMID * HW + (size_t)(g * CG) * HW;

#pragma unroll
    for (int conv = 0; conv < 2; conv++) {
        const float* offb = offs + (size_t)b * (2 * CMID) * HW
                            + (size_t)(conv ? CMID : 0) * HW;
        __nv_bfloat16* cH = (conv ? chh : cwh) + (size_t)b * KDIM_P * HW
                            + (size_t)(g * CG) * KK * HW + p;
        __nv_bfloat16* cL = (conv ? chl : cwl) + (size_t)b * KDIM_P * HW
                            + (size_t)(g * CG) * KK * HW + p;

#pragma unroll
        for (int kk = 0; kk < KK; kk++) {
            float oy = offb[(size_t)(g * 18 + kk * 2 + 0) * HW + p];
            float ox = offb[(size_t)(g * 18 + kk * 2 + 1) * HW + p];
            float sy = oy + (float)(kk / 3 - 1 + h);
            float sx = ox + (float)(kk % 3 - 1 + w);
            float y0f = floorf(sy), x0f = floorf(sx);
            float dy = sy - y0f, dx = sx - x0f;
            int y0 = (int)y0f, x0 = (int)x0f;
            int y1 = y0 + 1, x1 = x0 + 1;
            bool vy0 = (y0 >= 0) & (y0 < Hh);
            bool vy1 = (y1 >= 0) & (y1 < Hh);
            bool vx0 = (x0 >= 0) & (x0 < Ww);
            bool vx1 = (x1 >= 0) & (x1 < Ww);
            int y0c = min(max(y0, 0), Hh - 1);
            int y1c = min(max(y1, 0), Hh - 1);
            int x0c = min(max(x0, 0), Ww - 1);
            int x1c = min(max(x1, 0), Ww - 1);
            float w00 = (1.f - dy) * (1.f - dx) * (float)(vy0 && vx0);
            float w01 = (1.f - dy) * dx        * (float)(vy0 && vx1);
            float w10 = dy * (1.f - dx)        * (float)(vy1 && vx0);
            float w11 = dy * dx                * (float)(vy1 && vx1);
            int i00 = y0c * Ww + x0c, i01 = y0c * Ww + x1c;
            int i10 = y1c * Ww + x0c, i11 = y1c * Ww + x1c;

#pragma unroll
            for (int c = 0; c < CG; c++) {
                const float* xc = xb + (size_t)c * HW;
                float v = w00 * xc[i00] + w01 * xc[i01]
                        + w10 * xc[i10] + w11 * xc[i11];
                __nv_bfloat16 hv, lv;
                split_bf16(v, hv, lv);
                cH[(size_t)(c * KK + kk) * HW] = hv;
                cL[(size_t)(c * KK + kk) * HW] = lv;
            }
        }
    }
}

// ---------------- mean over HW of (fw+fh) per (b,c) ----------------
__global__ void reduce_mean_kernel(const float* __restrict__ fw,
                                   const float* __restrict__ fh,
                                   float* __restrict__ avg)
{
    const int bc = blockIdx.x;
    const float* a = fw + (size_t)bc * HW;
    const float* b = fh + (size_t)bc * HW;
    float s = 0.f;
    for (int i = threadIdx.x; i < HW; i += 256) s += a[i] + b[i];
    __shared__ float sm[256];
    sm[threadIdx.x] = s;
    __syncthreads();
    for (int st = 128; st > 0; st >>= 1) {
        if (threadIdx.x < st) sm[threadIdx.x] += sm[threadIdx.x + st];
        __syncthreads();
    }
    if (threadIdx.x == 0) avg[bc] = sm[0] * (1.0f / HW);
}

// ---------------- attention softmax ----------------
__global__ void attn_kernel(const float* __restrict__ avg,
                            const float* __restrict__ w_attn,
                            const float* __restrict__ b_attn,
                            float* __restrict__ attn)
{
    const int t = threadIdx.x;
    __shared__ float logits[4];
    if (t < 4) {
        int b = t >> 1, o = t & 1;
        float s = b_attn[o];
        for (int c = 0; c < CMID; c++)
            s += avg[b * CMID + c] * w_attn[o * CMID + c];
        logits[t] = s;
    }
    __syncthreads();
    if (t < 2) {
        float l0 = logits[t * 2 + 0], l1 = logits[t * 2 + 1];
        float m = fmaxf(l0, l1);
        float e0 = expf(l0 - m), e1 = expf(l1 - m);
        float inv = 1.f / (e0 + e1);
        attn[t * 2 + 0] = e0 * inv;   // f_h weight
        attn[t * 2 + 1] = e1 * inv;   // f_w weight
    }
}

// ---------------- attention mix -> bf16 hi/lo planes ----------------
__global__ void mix_kernel(const float* __restrict__ fh, const float* __restrict__ fw,
                           const float* __restrict__ attn,
                           __nv_bfloat16* __restrict__ mh, __nv_bfloat16* __restrict__ ml)
{
    size_t i = (size_t)blockIdx.x * blockDim.x + threadIdx.x;
    if (i >= (size_t)B * CMID * HW) return;
    int z = (int)(i / ((size_t)CMID * HW));
    size_t rem = i - (size_t)z * CMID * HW;
    float v = attn[z * 2] * fh[i] + attn[z * 2 + 1] * fw[i];
    __nv_bfloat16 h, l;
    split_bf16(v, h, l);
    size_t d = (size_t)z * 192 * HW + rem;
    mh[d] = h;
    ml[d] = l;
}

// ---------------- launcher ----------------
extern "C" void kernel_launch(void* const* d_in, const int* in_sizes, int n_in,
                              void* d_out, int out_size)
{
    const float* x        = (const float*)d_in[0];
    const float* w_reduce = (const float*)d_in[1];
    const float* b_reduce = (const float*)d_in[2];
    const float* w_offset = (const float*)d_in[3];
    const float* b_offset = (const float*)d_in[4];
    const float* w_dcnw   = (const float*)d_in[5];
    const float* b_dcnw   = (const float*)d_in[6];
    const float* w_dcnh   = (const float*)d_in[7];
    const float* b_dcnh   = (const float*)d_in[8];
    const float* w_expand = (const float*)d_in[9];
    const float* b_expand = (const float*)d_in[10];
    const float* w_attn   = (const float*)d_in[11];
    const float* b_attn   = (const float*)d_in[12];
    float* out = (float*)d_out;

    float *xr, *offs, *fw, *fh, *avg, *attn;
    cudaGetSymbolAddress((void**)&xr,   g_xr);
    cudaGetSymbolAddress((void**)&offs, g_offs);
    cudaGetSymbolAddress((void**)&fw,   g_fw);
    cudaGetSymbolAddress((void**)&fh,   g_fh);
    cudaGetSymbolAddress((void**)&avg,  g_avg);
    cudaGetSymbolAddress((void**)&attn, g_attn);
    __nv_bfloat16 *xpH, *xpL, *xrpH, *xrpL, *cwH, *cwL, *chH, *chL, *mxH, *mxL;
    cudaGetSymbolAddress((void**)&xpH,  g_xp_h);
    cudaGetSymbolAddress((void**)&xpL,  g_xp_l);
    cudaGetSymbolAddress((void**)&xrpH, g_xrp_h);
    cudaGetSymbolAddress((void**)&xrpL, g_xrp_l);
    cudaGetSymbolAddress((void**)&cwH,  g_cw_h);
    cudaGetSymbolAddress((void**)&cwL,  g_cw_l);
    cudaGetSymbolAddress((void**)&chH,  g_ch_h);
    cudaGetSymbolAddress((void**)&chL,  g_ch_l);
    cudaGetSymbolAddress((void**)&mxH,  g_mx_h);
    cudaGetSymbolAddress((void**)&mxL,  g_mx_l);
    __nv_bfloat16 *wpR, *wpO, *wpW, *wpH, *wpE;
    cudaGetSymbolAddress((void**)&wpR, g_wpR);
    cudaGetSymbolAddress((void**)&wpO, g_wpO);
    cudaGetSymbolAddress((void**)&wpW, g_wpW);
    cudaGetSymbolAddress((void**)&wpH, g_wpH);
    cudaGetSymbolAddress((void**)&wpE, g_wpE);

    cudaFuncSetAttribute(tgemm_kernel<false>,
                         cudaFuncAttributeMaxDynamicSharedMemorySize, SMEM_BYTES);
    cudaFuncSetAttribute(tgemm_kernel<true>,
                         cudaFuncAttributeMaxDynamicSharedMemorySize, SMEM_BYTES);

    // 0) prepack weights + convert x
    auto pgrid = [](int n) { return dim3((n + 255) / 256); };
    prepack_kernel<<<pgrid(192 * 192),  256>>>(w_reduce,  192, 180, 192, 192, wpR);
    prepack_kernel<<<pgrid(192 * 384),  256>>>(w_offset,  180, 360, 384, 192, wpO);
    prepack_kernel<<<pgrid(1664 * 192), 256>>>(w_dcnw,   1620, 180, 192, 1664, wpW);
    prepack_kernel<<<pgrid(1664 * 192), 256>>>(w_dcnh,   1620, 180, 192, 1664, wpH);
    prepack_kernel<<<pgrid(192 * 192),  256>>>(w_expand,  180, 192, 192, 192, wpE);
    {
        size_t n = (size_t)B * CIN * HW;
        convert_x_kernel<<<(unsigned)((n + 255) / 256), 256>>>(x, xpH, xpL, n);
    }

    // 1) xr = reduce(x): M=180(pad192), K=192; also emit xr planes
    tgemm_kernel<true><<<dim3(72, 3, B), 256, SMEM_BYTES>>>(
        xpH, xpL, (size_t)192 * HW, wpR, 6, b_reduce, 180,
        xr, (size_t)CMID * HW, xrpH, xrpL, (size_t)192 * HW);

    // 2) offs = offset(xr): M=360(pad384), K=180(pad192)
    tgemm_kernel<false><<<dim3(72, 6, B), 256, SMEM_BYTES>>>(
        xrpH, xrpL, (size_t)192 * HW, wpO, 6, b_offset, 360,
        offs, (size_t)2 * CMID * HW, nullptr, nullptr, 0);

    // 3) im2col -> hi/lo col planes (both convs)
    im2col_deform_kernel<<<dim3(HW / 256, G, B), 256>>>(xr, offs, cwH, cwL, chH, chL);

    // 4) deform GEMMs: M=180(pad192), K=1620(pad1664)
    tgemm_kernel<false><<<dim3(72, 3, B), 256, SMEM_BYTES>>>(
        cwH, cwL, (size_t)KDIM_P * HW, wpW, 52, b_dcnw, 180,
        fw, (size_t)CMID * HW, nullptr, nullptr, 0);
    tgemm_kernel<false><<<dim3(72, 3, B), 256, SMEM_BYTES>>>(
        chH, chL, (size_t)KDIM_P * HW, wpH, 52, b_dcnh, 180,
        fh, (size_t)CMID * HW, nullptr, nullptr, 0);

    // 5) attention
    reduce_mean_kernel<<<B * CMID, 256>>>(fw, fh, avg);
    attn_kernel<<<1, 64>>>(avg, w_attn, b_attn, attn);
    {
        size_t n = (size_t)B * CMID * HW;
        mix_kernel<<<(unsigned)((n + 255) / 256), 256>>>(fh, fw, attn, mxH, mxL);
    }

    // 6) out = expand(mix): M=192, K=180(pad192)
    tgemm_kernel<false><<<dim3(72, 3, B), 256, SMEM_BYTES>>>(
        mxH, mxL, (size_t)192 * HW, wpE, 6, b_expand, 192,
        out, (size_t)CIN * HW, nullptr, nullptr, 0);
}

// round 6
// speedup vs baseline: 4.8113x; 1.2908x over previous
#include <cuda_runtime.h>
#include <cuda_fp16.h>
#include <math.h>
#include <stdint.h>

// ---------------- problem constants ----------------
constexpr int B    = 2;
constexpr int CIN  = 192;
constexpr int CMID = 180;
constexpr int Hh   = 96;
constexpr int Ww   = 96;
constexpr int HW   = Hh * Ww;          // 9216
constexpr int KK   = 9;
constexpr int G    = 10;
constexpr int CG   = CMID / G;         // 18
constexpr int KDIM = CMID * KK;        // 1620
constexpr int KDIM_P = 1664;           // 52 chunks of 32

constexpr size_t FSTR = (size_t)192 * HW;      // xr/fw/fh stride (pad rows zero)
constexpr size_t OSTR = (size_t)360 * HW;      // offs stride
constexpr size_t CSTR = (size_t)KDIM_P * HW;   // col plane stride

// ---------------- device scratch (zero-initialized statics) ----------------
__device__ __align__(256) float g_xr  [(size_t)B * FSTR];
__device__ __align__(256) float g_offs[(size_t)B * OSTR];
__device__ __align__(256) float g_fw  [(size_t)B * FSTR];
__device__ __align__(256) float g_fh  [(size_t)B * FSTR];
__device__ float g_avg [B * CMID];
__device__ float g_attn[B * 2];
// fp16 activation planes (pad rows stay zero forever)
__device__ __align__(256) __half g_xp  [(size_t)B * 192 * HW];
__device__ __align__(256) __half g_xrp [(size_t)B * FSTR];
__device__ __align__(256) __half g_cw  [(size_t)B * CSTR];
__device__ __align__(256) __half g_ch  [(size_t)B * CSTR];
// prepacked weights: [plane(hi,lo)][Kpad][Mpad] k-major
__device__ __align__(256) __half g_wpR[2 * 192  * 192];
__device__ __align__(256) __half g_wpO[2 * 192  * 384];
__device__ __align__(256) __half g_wpW[2 * 1664 * 192];
__device__ __align__(256) __half g_wpH[2 * 1664 * 192];
__device__ __align__(256) __half g_wpE[2 * 192  * 192];

// ---------------- PTX helpers (arch-generic) ----------------
__device__ __forceinline__ uint32_t smem_to_u32(const void* p) {
    uint32_t a;
    asm("{ .reg .u64 t; cvta.to.shared.u64 t, %1; cvt.u32.u64 %0, t; }"
        : "=r"(a) : "l"(p));
    return a;
}
__device__ __forceinline__ void cp16(uint32_t dst, const void* src) {
    asm volatile("cp.async.cg.shared.global [%0], [%1], 16;" :: "r"(dst), "l"(src));
}
#define CP_COMMIT() asm volatile("cp.async.commit_group;" ::: "memory")
#define CP_WAIT(n)  asm volatile("cp.async.wait_group %0;" :: "n"(n) : "memory")

__device__ __forceinline__ void ldsm_x4_t(uint32_t* r, uint32_t addr) {
    asm volatile("ldmatrix.sync.aligned.m8n8.x4.trans.shared.b16 {%0,%1,%2,%3}, [%4];"
        : "=r"(r[0]), "=r"(r[1]), "=r"(r[2]), "=r"(r[3]) : "r"(addr));
}
__device__ __forceinline__ void mma16816(float* d, const uint32_t* a, const uint32_t* b) {
    asm volatile("mma.sync.aligned.m16n8k16.row.col.f32.f16.f16.f32 "
        "{%0,%1,%2,%3}, {%4,%5,%6,%7}, {%8,%9}, {%0,%1,%2,%3};"
        : "+f"(d[0]), "+f"(d[1]), "+f"(d[2]), "+f"(d[3])
        : "r"(a[0]), "r"(a[1]), "r"(a[2]), "r"(a[3]), "r"(b[0]), "r"(b[1]));
}

// SMEM layout:
//  A (weights): 2 bufs x (2 planes x 32 rows x 400B) = 51200   (buf stride 25600)
//  B (acts)   : 2 bufs x (32 rows x 272B)            = 17408   (buf stride 8704)
constexpr int SMB_B = 51200;
constexpr int B_BUF_STRIDE = 8704;
constexpr int SMEM_BYTES = 51200 + 17408;   // 68608

// ---------------- tensor GEMM (fp16, weights hi/lo split = 2 passes) --------
// C[z][m][p] = sum_k W[m][k] * Act[z][k][p] + bias[m]
// grid = (72, Mpad/192, B), block = 256 (8 warps: 4m x 2n of 48x64 tiles)
template <bool PLANES, bool MIX>
__global__ void __launch_bounds__(256, 1)
tgemm_kernel(const __half* __restrict__ actp, size_t strideAct,
             const float* __restrict__ mA, const float* __restrict__ mB,
             const float* __restrict__ attnp,
             const __half* __restrict__ Wp, int nChunks,
             const float* __restrict__ bias, int Mvalid,
             float* __restrict__ outF, size_t strideOF,
             __half* __restrict__ outP, size_t strideOP)
{
    extern __shared__ char smem[];
    const uint32_t sb = smem_to_u32(smem);
    const int tid = threadIdx.x, lane = tid & 31, wid = tid >> 5;
    const int wm = wid & 3, wn = wid >> 2;
    const int z = blockIdx.z, yb = blockIdx.y;
    const int pbase = blockIdx.x * 128;
    const int Mpad = gridDim.y * 192;
    const size_t wPlane = (size_t)nChunks * 32 * Mpad;

    const __half* actz = MIX ? nullptr : (actp + (size_t)z * strideAct + pbase);
    const float* mAz = MIX ? (mA + (size_t)z * strideAct + pbase) : nullptr;
    const float* mBz = MIX ? (mB + (size_t)z * strideAct + pbase) : nullptr;
    float c0 = 0.f, c1 = 0.f;
    if (MIX) { c0 = attnp[z * 2]; c1 = attnp[z * 2 + 1]; }

    auto loadChunk = [&](int kc, int s) {
        // A: weights (both planes): 1536 x 16B
#pragma unroll
        for (int i = 0; i < 6; i++) {
            int c = tid + i * 256;
            int pl = c / 768, rem = c % 768, row = rem / 24, cc = rem % 24;
            uint32_t dst = sb + s * 25600 + pl * 12800 + row * 400 + cc * 16;
            const __half* src = Wp + (size_t)pl * wPlane
                + (size_t)(kc * 32 + row) * Mpad + yb * 192 + cc * 8;
            cp16(dst, src);
        }
        // B: activations: 512 x 16B
#pragma unroll
        for (int i = 0; i < 2; i++) {
            int c = tid + i * 256;
            int row = c >> 4, cc = c & 15;
            uint32_t dst = sb + SMB_B + s * B_BUF_STRIDE + row * 272 + cc * 16;
            if (!MIX) {
                cp16(dst, actz + (size_t)(kc * 32 + row) * HW + cc * 8);
            } else {
                size_t off = (size_t)(kc * 32 + row) * HW + cc * 8;
                float4 a0 = *reinterpret_cast<const float4*>(mAz + off);
                float4 a1 = *reinterpret_cast<const float4*>(mAz + off + 4);
                float4 b0 = *reinterpret_cast<const float4*>(mBz + off);
                float4 b1 = *reinterpret_cast<const float4*>(mBz + off + 4);
                __half2 h0 = __floats2half2_rn(c0 * a0.x + c1 * b0.x, c0 * a0.y + c1 * b0.y);
                __half2 h1 = __floats2half2_rn(c0 * a0.z + c1 * b0.z, c0 * a0.w + c1 * b0.w);
                __half2 h2 = __floats2half2_rn(c0 * a1.x + c1 * b1.x, c0 * a1.y + c1 * b1.y);
                __half2 h3 = __floats2half2_rn(c0 * a1.z + c1 * b1.z, c0 * a1.w + c1 * b1.w);
                asm volatile("st.shared.v4.b32 [%0], {%1, %2, %3, %4};"
                    :: "r"(dst),
                       "r"(*reinterpret_cast<uint32_t*>(&h0)),
                       "r"(*reinterpret_cast<uint32_t*>(&h1)),
                       "r"(*reinterpret_cast<uint32_t*>(&h2)),
                       "r"(*reinterpret_cast<uint32_t*>(&h3)) : "memory");
            }
        }
    };

    // ldmatrix per-lane addresses
    const uint32_t aRow  = ((lane >> 4) & 1) * 8 + (lane & 7);
    const uint32_t aColB = (uint32_t)(wm * 48 + ((lane >> 3) & 1) * 8) * 2;
    const uint32_t bRow  = ((lane >> 3) & 1) * 8 + (lane & 7);
    const uint32_t bColB = (uint32_t)(wn * 64 + ((lane >> 4) & 1) * 8) * 2;
    const uint32_t aAddr = sb + aRow * 400 + aColB;           // + mt*32, +pl*12800, +ks*6400
    const uint32_t bAddr = sb + SMB_B + bRow * 272 + bColB;   // + ntp*32, +ks*4352

    float acc[3][8][4];
#pragma unroll
    for (int i = 0; i < 3; i++)
#pragma unroll
        for (int j = 0; j < 8; j++)
#pragma unroll
            for (int q = 0; q < 4; q++) acc[i][j][q] = 0.f;

    loadChunk(0, 0);
    CP_COMMIT();

    for (int t = 0; t < nChunks; t++) {
        const int s = t & 1;
        if (t + 1 < nChunks) {
            loadChunk(t + 1, s ^ 1);
            CP_COMMIT();
            CP_WAIT(1);
        } else {
            CP_WAIT(0);
        }
        __syncthreads();

        const uint32_t aB = s * 25600, bB = s * B_BUF_STRIDE;
#pragma unroll
        for (int ks = 0; ks < 2; ks++) {
            uint32_t Ah[3][4], Al[3][4], Bf[4][4];
#pragma unroll
            for (int mt = 0; mt < 3; mt++) {
                ldsm_x4_t(Ah[mt], aAddr + aB + mt * 32 + ks * 6400);
                ldsm_x4_t(Al[mt], aAddr + aB + 12800 + mt * 32 + ks * 6400);
            }
#pragma unroll
            for (int ntp = 0; ntp < 4; ntp++)
                ldsm_x4_t(Bf[ntp], bAddr + bB + ntp * 32 + ks * 4352);
#pragma unroll
            for (int mt = 0; mt < 3; mt++)
#pragma unroll
                for (int nt = 0; nt < 8; nt++) {
                    const uint32_t* bp = &Bf[nt >> 1][(nt & 1) * 2];
                    mma16816(acc[mt][nt], Ah[mt], bp);   // w_hi * act
                    mma16816(acc[mt][nt], Al[mt], bp);   // w_lo * act
                }
        }
        __syncthreads();
    }

    // epilogue
    float* oF = outF + (size_t)z * strideOF;
    __half* oP = PLANES ? (outP + (size_t)z * strideOP) : nullptr;
#pragma unroll
    for (int mt = 0; mt < 3; mt++) {
#pragma unroll
        for (int half = 0; half < 2; half++) {
            const int m = yb * 192 + wm * 48 + mt * 16 + half * 8 + (lane >> 2);
            if (m < Mvalid) {
                const float bv = bias[m];
#pragma unroll
                for (int nt = 0; nt < 8; nt++) {
                    const int n0 = pbase + wn * 64 + nt * 8 + (lane & 3) * 2;
                    float v0 = acc[mt][nt][half * 2 + 0] + bv;
                    float v1 = acc[mt][nt][half * 2 + 1] + bv;
                    *reinterpret_cast<float2*>(&oF[(size_t)m * HW + n0]) =
                        make_float2(v0, v1);
                    if (PLANES) {
                        __half2 hv = __floats2half2_rn(v0, v1);
                        *reinterpret_cast<__half2*>(&oP[(size_t)m * HW + n0]) = hv;
                    }
                }
            }
        }
    }
}

// ---------------- weight prepack: [plane][Kpad][Mpad] fp16 hi/lo ------------
__global__ void prepack_kernel(const float* __restrict__ W, int Kd, int Mvalid,
                               int Mpad, int Kpad, __half* __restrict__ dst)
{
    int idx = blockIdx.x * blockDim.x + threadIdx.x;
    if (idx >= Kpad * Mpad) return;
    int k = idx / Mpad, m = idx % Mpad;
    float v = (k < Kd && m < Mvalid) ? W[(size_t)m * Kd + k] : 0.f;
    __half h = __float2half_rn(v);
    __half l = __float2half_rn(v - __half2float(h));
    dst[idx] = h;
    dst[(size_t)Kpad * Mpad + idx] = l;
}

// ---------------- x -> fp16 plane ----------------
__global__ void convert_x_kernel(const float* __restrict__ x,
                                 __half* __restrict__ p, size_t n)
{
    size_t i = (size_t)blockIdx.x * blockDim.x + threadIdx.x;
    if (i >= n) return;
    p[i] = __float2half_rn(x[i]);
}

// ---------------- deformable im2col -> fp16 col planes ----------------
__global__ void __launch_bounds__(256)
im2col_deform_kernel(const float* __restrict__ xr, const float* __restrict__ offs,
                     __half* __restrict__ cw, __half* __restrict__ ch)
{
    const int b = blockIdx.z;
    const int g = blockIdx.y;
    const int p = blockIdx.x * blockDim.x + threadIdx.x;
    if (p >= HW) return;
    const int h = p / Ww, w = p % Ww;

    const float* xb = xr + (size_t)b * FSTR + (size_t)(g * CG) * HW;

#pragma unroll
    for (int conv = 0; conv < 2; conv++) {
        const float* offb = offs + (size_t)b * OSTR + (size_t)(conv ? CMID : 0) * HW;
        __half* colb = (conv ? ch : cw) + (size_t)b * CSTR
                       + (size_t)(g * CG) * KK * HW + p;

#pragma unroll
        for (int kk = 0; kk < KK; kk++) {
            float oy = offb[(size_t)(g * 18 + kk * 2 + 0) * HW + p];
            float ox = offb[(size_t)(g * 18 + kk * 2 + 1) * HW + p];
            float sy = oy + (float)(kk / 3 - 1 + h);
            float sx = ox + (float)(kk % 3 - 1 + w);
            float y0f = floorf(sy), x0f = floorf(sx);
            float dy = sy - y0f, dx = sx - x0f;
            int y0 = (int)y0f, x0 = (int)x0f;
            int y1 = y0 + 1, x1 = x0 + 1;
            bool vy0 = (y0 >= 0) & (y0 < Hh);
            bool vy1 = (y1 >= 0) & (y1 < Hh);
            bool vx0 = (x0 >= 0) & (x0 < Ww);
            bool vx1 = (x1 >= 0) & (x1 < Ww);
            int y0c = min(max(y0, 0), Hh - 1);
            int y1c = min(max(y1, 0), Hh - 1);
            int x0c = min(max(x0, 0), Ww - 1);
            int x1c = min(max(x1, 0), Ww - 1);
            float w00 = (1.f - dy) * (1.f - dx) * (float)(vy0 && vx0);
            float w01 = (1.f - dy) * dx        * (float)(vy0 && vx1);
            float w10 = dy * (1.f - dx)        * (float)(vy1 && vx0);
            float w11 = dy * dx                * (float)(vy1 && vx1);
            int i00 = y0c * Ww + x0c, i01 = y0c * Ww + x1c;
            int i10 = y1c * Ww + x0c, i11 = y1c * Ww + x1c;

#pragma unroll
            for (int c = 0; c < CG; c++) {
                const float* xc = xb + (size_t)c * HW;
                float v = w00 * xc[i00] + w01 * xc[i01]
                        + w10 * xc[i10] + w11 * xc[i11];
                colb[(size_t)(c * KK + kk) * HW] = __float2half_rn(v);
            }
        }
    }
}

// ---------------- mean over HW of (fw+fh) per (b,c) ----------------
__global__ void reduce_mean_kernel(const float* __restrict__ fw,
                                   const float* __restrict__ fh,
                                   float* __restrict__ avg)
{
    const int bc = blockIdx.x;
    const int bb = bc / CMID, cc = bc % CMID;
    const float* a = fw + (size_t)bb * FSTR + (size_t)cc * HW;
    const float* b = fh + (size_t)bb * FSTR + (size_t)cc * HW;
    float s = 0.f;
    for (int i = threadIdx.x; i < HW; i += 256) s += a[i] + b[i];
    __shared__ float sm[256];
    sm[threadIdx.x] = s;
    __syncthreads();
    for (int st = 128; st > 0; st >>= 1) {
        if (threadIdx.x < st) sm[threadIdx.x] += sm[threadIdx.x + st];
        __syncthreads();
    }
    if (threadIdx.x == 0) avg[bc] = sm[0] * (1.0f / HW);
}

// ---------------- attention softmax ----------------
__global__ void attn_kernel(const float* __restrict__ avg,
                            const float* __restrict__ w_attn,
                            const float* __restrict__ b_attn,
                            float* __restrict__ attn)
{
    const int t = threadIdx.x;
    __shared__ float logits[4];
    if (t < 4) {
        int b = t >> 1, o = t & 1;
        float s = b_attn[o];
        for (int c = 0; c < CMID; c++)
            s += avg[b * CMID + c] * w_attn[o * CMID + c];
        logits[t] = s;
    }
    __syncthreads();
    if (t < 2) {
        float l0 = logits[t * 2 + 0], l1 = logits[t * 2 + 1];
        float m = fmaxf(l0, l1);
        float e0 = expf(l0 - m), e1 = expf(l1 - m);
        float inv = 1.f / (e0 + e1);
        attn[t * 2 + 0] = e0 * inv;   // f_h weight
        attn[t * 2 + 1] = e1 * inv;   // f_w weight
    }
}

// ---------------- launcher ----------------
extern "C" void kernel_launch(void* const* d_in, const int* in_sizes, int n_in,
                              void* d_out, int out_size)
{
    const float* x        = (const float*)d_in[0];
    const float* w_reduce = (const float*)d_in[1];
    const float* b_reduce = (const float*)d_in[2];
    const float* w_offset = (const float*)d_in[3];
    const float* b_offset = (const float*)d_in[4];
    const float* w_dcnw   = (const float*)d_in[5];
    const float* b_dcnw   = (const float*)d_in[6];
    const float* w_dcnh   = (const float*)d_in[7];
    const float* b_dcnh   = (const float*)d_in[8];
    const float* w_expand = (const float*)d_in[9];
    const float* b_expand = (const float*)d_in[10];
    const float* w_attn   = (const float*)d_in[11];
    const float* b_attn   = (const float*)d_in[12];
    float* out = (float*)d_out;

    float *xr, *offs, *fw, *fh, *avg, *attn;
    cudaGetSymbolAddress((void**)&xr,   g_xr);
    cudaGetSymbolAddress((void**)&offs, g_offs);
    cudaGetSymbolAddress((void**)&fw,   g_fw);
    cudaGetSymbolAddress((void**)&fh,   g_fh);
    cudaGetSymbolAddress((void**)&avg,  g_avg);
    cudaGetSymbolAddress((void**)&attn, g_attn);
    __half *xp, *xrp, *cw, *ch, *wpR, *wpO, *wpW, *wpH, *wpE;
    cudaGetSymbolAddress((void**)&xp,  g_xp);
    cudaGetSymbolAddress((void**)&xrp, g_xrp);
    cudaGetSymbolAddress((void**)&cw,  g_cw);
    cudaGetSymbolAddress((void**)&ch,  g_ch);
    cudaGetSymbolAddress((void**)&wpR, g_wpR);
    cudaGetSymbolAddress((void**)&wpO, g_wpO);
    cudaGetSymbolAddress((void**)&wpW, g_wpW);
    cudaGetSymbolAddress((void**)&wpH, g_wpH);
    cudaGetSymbolAddress((void**)&wpE, g_wpE);

    cudaFuncSetAttribute(tgemm_kernel<true,  false>,
                         cudaFuncAttributeMaxDynamicSharedMemorySize, SMEM_BYTES);
    cudaFuncSetAttribute(tgemm_kernel<false, false>,
                         cudaFuncAttributeMaxDynamicSharedMemorySize, SMEM_BYTES);
    cudaFuncSetAttribute(tgemm_kernel<false, true>,
                         cudaFuncAttributeMaxDynamicSharedMemorySize, SMEM_BYTES);

    // 0) prepack weights + convert x
    auto pgrid = [](int n) { return dim3((n + 255) / 256); };
    prepack_kernel<<<pgrid(192 * 192),  256>>>(w_reduce,  192, 180, 192, 192,  wpR);
    prepack_kernel<<<pgrid(192 * 384),  256>>>(w_offset,  180, 360, 384, 192,  wpO);
    prepack_kernel<<<pgrid(1664 * 192), 256>>>(w_dcnw,   1620, 180, 192, 1664, wpW);
    prepack_kernel<<<pgrid(1664 * 192), 256>>>(w_dcnh,   1620, 180, 192, 1664, wpH);
    prepack_kernel<<<pgrid(192 * 192),  256>>>(w_expand,  180, 192, 192, 192,  wpE);
    {
        size_t n = (size_t)B * CIN * HW;
        convert_x_kernel<<<(unsigned)((n + 255) / 256), 256>>>(x, xp, n);
    }

    // 1) xr = reduce(x): M=180(pad192), K=192; emits xr f32 + fp16 plane
    tgemm_kernel<true, false><<<dim3(72, 1, B), 256, SMEM_BYTES>>>(
        xp, (size_t)192 * HW, nullptr, nullptr, nullptr,
        wpR, 6, b_reduce, 180, xr, FSTR, xrp, FSTR);

    // 2) offs = offset(xr): M=360(pad384), K=180(pad192)
    tgemm_kernel<false, false><<<dim3(72, 2, B), 256, SMEM_BYTES>>>(
        xrp, FSTR, nullptr, nullptr, nullptr,
        wpO, 6, b_offset, 360, offs, OSTR, nullptr, 0);

    // 3) im2col -> fp16 col planes (both convs)
    im2col_deform_kernel<<<dim3(HW / 256, G, B), 256>>>(xr, offs, cw, ch);

    // 4) deform GEMMs: M=180(pad192), K=1620(pad1664)
    tgemm_kernel<false, false><<<dim3(72, 1, B), 256, SMEM_BYTES>>>(
        cw, CSTR, nullptr, nullptr, nullptr,
        wpW, 52, b_dcnw, 180, fw, FSTR, nullptr, 0);
    tgemm_kernel<false, false><<<dim3(72, 1, B), 256, SMEM_BYTES>>>(
        ch, CSTR, nullptr, nullptr, nullptr,
        wpH, 52, b_dcnh, 180, fh, FSTR, nullptr, 0);

    // 5) attention
    reduce_mean_kernel<<<B * CMID, 256>>>(fw, fh, avg);
    attn_kernel<<<1, 64>>>(avg, w_attn, b_attn, attn);

    // 6) out = expand(attn0*f_h + attn1*f_w): mix fused into B-loader
    tgemm_kernel<false, true><<<dim3(72, 1, B), 256, SMEM_BYTES>>>(
        nullptr, FSTR, fh, fw, attn,
        wpE, 6, b_expand, 192, out, (size_t)CIN * HW, nullptr, 0);
}

// round 7
// speedup vs baseline: 6.0926x; 1.2663x over previous
#include <cuda_runtime.h>
#include <cuda_fp16.h>
#include <math.h>
#include <stdint.h>

// ---------------- problem constants ----------------
constexpr int B    = 2;
constexpr int CIN  = 192;
constexpr int CMID = 180;
constexpr int Hh   = 96;
constexpr int Ww   = 96;
constexpr int HW   = Hh * Ww;          // 9216
constexpr int KK   = 9;
constexpr int G    = 10;
constexpr int CG   = CMID / G;         // 18
constexpr int KDIM = CMID * KK;        // 1620
constexpr int KDIM_P = 1632;           // 51 chunks of 32

constexpr size_t FSTR = (size_t)192 * HW;      // xr/fw/fh stride (pad rows zero)
constexpr size_t OSTR = (size_t)360 * HW;      // offs stride
constexpr size_t CSTR = (size_t)KDIM_P * HW;   // col plane stride

// ---------------- device scratch (zero-initialized statics) ----------------
__device__ __align__(256) float g_xr  [(size_t)B * FSTR];
__device__ __align__(256) float g_offs[(size_t)B * OSTR];
__device__ __align__(256) float g_fw  [(size_t)B * FSTR];
__device__ __align__(256) float g_fh  [(size_t)B * FSTR];
__device__ float g_avg [B * CMID];
__device__ float g_attn[B * 2];
// fp16 activation planes (pad rows stay zero forever)
__device__ __align__(256) __half g_xp  [(size_t)B * 192 * HW];
__device__ __align__(256) __half g_xrp [(size_t)B * FSTR];
__device__ __align__(256) __half g_cw  [(size_t)B * CSTR];
__device__ __align__(256) __half g_ch  [(size_t)B * CSTR];
// prepacked weights: [plane(hi,lo)][Kpad][Mpad] k-major (lo plane unused for 1-pass)
__device__ __align__(256) __half g_wpR[2 * 192  * 192];
__device__ __align__(256) __half g_wpO[2 * 192  * 384];
__device__ __align__(256) __half g_wpW[2 * 1632 * 192];
__device__ __align__(256) __half g_wpH[2 * 1632 * 192];
__device__ __align__(256) __half g_wpE[2 * 192  * 192];

// ---------------- PTX helpers (arch-generic) ----------------
__device__ __forceinline__ uint32_t smem_to_u32(const void* p) {
    uint32_t a;
    asm("{ .reg .u64 t; cvta.to.shared.u64 t, %1; cvt.u32.u64 %0, t; }"
        : "=r"(a) : "l"(p));
    return a;
}
__device__ __forceinline__ void cp16(uint32_t dst, const void* src) {
    asm volatile("cp.async.cg.shared.global [%0], [%1], 16;" :: "r"(dst), "l"(src));
}
#define CP_COMMIT() asm volatile("cp.async.commit_group;" ::: "memory")
#define CP_WAIT(n)  asm volatile("cp.async.wait_group %0;" :: "n"(n) : "memory")

__device__ __forceinline__ void ldsm_x4_t(uint32_t* r, uint32_t addr) {
    asm volatile("ldmatrix.sync.aligned.m8n8.x4.trans.shared.b16 {%0,%1,%2,%3}, [%4];"
        : "=r"(r[0]), "=r"(r[1]), "=r"(r[2]), "=r"(r[3]) : "r"(addr));
}
__device__ __forceinline__ void mma16816(float* d, const uint32_t* a, const uint32_t* b) {
    asm volatile("mma.sync.aligned.m16n8k16.row.col.f32.f16.f16.f32 "
        "{%0,%1,%2,%3}, {%4,%5,%6,%7}, {%8,%9}, {%0,%1,%2,%3};"
        : "+f"(d[0]), "+f"(d[1]), "+f"(d[2]), "+f"(d[3])
        : "r"(a[0]), "r"(a[1]), "r"(a[2]), "r"(a[3]), "r"(b[0]), "r"(b[1]));
}

// ---------------- tensor GEMM (fp16; PASSES=2 adds weight-lo correction) ----
// C[z][m][p] = sum_k W[m][k] * Act[z][k][p] + bias[m]
// grid = (72, Mpad/192, B), block = 256 (8 warps: 4m x 2n of 48x64 tiles)
// SMEM: A = 2 bufs x PASSES planes x (32 rows x 400B = 12800B); B = 2 bufs x 8704B
template <int PASSES, bool PLANES, bool MIX>
__global__ void __launch_bounds__(256, 1)
tgemm_kernel(const __half* __restrict__ actp, size_t strideAct,
             const float* __restrict__ mA, const float* __restrict__ mB,
             const float* __restrict__ attnp,
             const __half* __restrict__ Wp, int nChunks,
             const float* __restrict__ bias, int Mvalid,
             float* __restrict__ outF, size_t strideOF,
             __half* __restrict__ outP, size_t strideOP)
{
    constexpr int A_BUF = PASSES * 12800;
    constexpr int SMB_B = 2 * A_BUF;
    extern __shared__ char smem[];
    const uint32_t sb = smem_to_u32(smem);
    const int tid = threadIdx.x, lane = tid & 31, wid = tid >> 5;
    const int wm = wid & 3, wn = wid >> 2;
    const int z = blockIdx.z, yb = blockIdx.y;
    const int pbase = blockIdx.x * 128;
    const int Mpad = gridDim.y * 192;
    const size_t wPlane = (size_t)nChunks * 32 * Mpad;

    const __half* actz = MIX ? nullptr : (actp + (size_t)z * strideAct + pbase);
    const float* mAz = MIX ? (mA + (size_t)z * strideAct + pbase) : nullptr;
    const float* mBz = MIX ? (mB + (size_t)z * strideAct + pbase) : nullptr;
    float c0 = 0.f, c1 = 0.f;
    if (MIX) { c0 = attnp[z * 2]; c1 = attnp[z * 2 + 1]; }

    auto loadChunk = [&](int kc, int s) {
        // A: weights (PASSES planes): PASSES*768 x 16B
#pragma unroll
        for (int i = 0; i < 3 * PASSES; i++) {
            int c = tid + i * 256;
            int pl = c / 768, rem = c % 768, row = rem / 24, cc = rem % 24;
            uint32_t dst = sb + s * A_BUF + pl * 12800 + row * 400 + cc * 16;
            const __half* src = Wp + (size_t)pl * wPlane
                + (size_t)(kc * 32 + row) * Mpad + yb * 192 + cc * 8;
            cp16(dst, src);
        }
        // B: activations: 512 x 16B
#pragma unroll
        for (int i = 0; i < 2; i++) {
            int c = tid + i * 256;
            int row = c >> 4, cc = c & 15;
            uint32_t dst = sb + SMB_B + s * 8704 + row * 272 + cc * 16;
            if (!MIX) {
                cp16(dst, actz + (size_t)(kc * 32 + row) * HW + cc * 8);
            } else {
                size_t off = (size_t)(kc * 32 + row) * HW + cc * 8;
                float4 a0 = *reinterpret_cast<const float4*>(mAz + off);
                float4 a1 = *reinterpret_cast<const float4*>(mAz + off + 4);
                float4 b0 = *reinterpret_cast<const float4*>(mBz + off);
                float4 b1 = *reinterpret_cast<const float4*>(mBz + off + 4);
                __half2 h0 = __floats2half2_rn(c0 * a0.x + c1 * b0.x, c0 * a0.y + c1 * b0.y);
                __half2 h1 = __floats2half2_rn(c0 * a0.z + c1 * b0.z, c0 * a0.w + c1 * b0.w);
                __half2 h2 = __floats2half2_rn(c0 * a1.x + c1 * b1.x, c0 * a1.y + c1 * b1.y);
                __half2 h3 = __floats2half2_rn(c0 * a1.z + c1 * b1.z, c0 * a1.w + c1 * b1.w);
                asm volatile("st.shared.v4.b32 [%0], {%1, %2, %3, %4};"
                    :: "r"(dst),
                       "r"(*reinterpret_cast<uint32_t*>(&h0)),
                       "r"(*reinterpret_cast<uint32_t*>(&h1)),
                       "r"(*reinterpret_cast<uint32_t*>(&h2)),
                       "r"(*reinterpret_cast<uint32_t*>(&h3)) : "memory");
            }
        }
    };

    // ldmatrix per-lane addresses
    const uint32_t aRow  = ((lane >> 4) & 1) * 8 + (lane & 7);
    const uint32_t aColB = (uint32_t)(wm * 48 + ((lane >> 3) & 1) * 8) * 2;
    const uint32_t bRow  = ((lane >> 3) & 1) * 8 + (lane & 7);
    const uint32_t bColB = (uint32_t)(wn * 64 + ((lane >> 4) & 1) * 8) * 2;
    const uint32_t aAddr = sb + aRow * 400 + aColB;           // + mt*32, +pl*12800, +ks*6400
    const uint32_t bAddr = sb + SMB_B + bRow * 272 + bColB;   // + ntp*32, +ks*4352

    float acc[3][8][4];
#pragma unroll
    for (int i = 0; i < 3; i++)
#pragma unroll
        for (int j = 0; j < 8; j++)
#pragma unroll
            for (int q = 0; q < 4; q++) acc[i][j][q] = 0.f;

    loadChunk(0, 0);
    CP_COMMIT();

    for (int t = 0; t < nChunks; t++) {
        const int s = t & 1;
        if (t + 1 < nChunks) {
            loadChunk(t + 1, s ^ 1);
            CP_COMMIT();
            CP_WAIT(1);
        } else {
            CP_WAIT(0);
        }
        __syncthreads();

        const uint32_t aB = s * A_BUF, bB = s * 8704;
#pragma unroll
        for (int ks = 0; ks < 2; ks++) {
            uint32_t Ah[3][4], Al[3][4], Bf[4][4];
#pragma unroll
            for (int mt = 0; mt < 3; mt++) {
                ldsm_x4_t(Ah[mt], aAddr + aB + mt * 32 + ks * 6400);
                if (PASSES == 2)
                    ldsm_x4_t(Al[mt], aAddr + aB + 12800 + mt * 32 + ks * 6400);
            }
#pragma unroll
            for (int ntp = 0; ntp < 4; ntp++)
                ldsm_x4_t(Bf[ntp], bAddr + bB + ntp * 32 + ks * 4352);
#pragma unroll
            for (int mt = 0; mt < 3; mt++)
#pragma unroll
                for (int nt = 0; nt < 8; nt++) {
                    const uint32_t* bp = &Bf[nt >> 1][(nt & 1) * 2];
                    mma16816(acc[mt][nt], Ah[mt], bp);   // w_hi * act
                    if (PASSES == 2)
                        mma16816(acc[mt][nt], Al[mt], bp);   // w_lo * act
                }
        }
        __syncthreads();
    }

    // epilogue
    float* oF = outF + (size_t)z * strideOF;
    __half* oP = PLANES ? (outP + (size_t)z * strideOP) : nullptr;
#pragma unroll
    for (int mt = 0; mt < 3; mt++) {
#pragma unroll
        for (int half = 0; half < 2; half++) {
            const int m = yb * 192 + wm * 48 + mt * 16 + half * 8 + (lane >> 2);
            if (m < Mvalid) {
                const float bv = bias[m];
#pragma unroll
                for (int nt = 0; nt < 8; nt++) {
                    const int n0 = pbase + wn * 64 + nt * 8 + (lane & 3) * 2;
                    float v0 = acc[mt][nt][half * 2 + 0] + bv;
                    float v1 = acc[mt][nt][half * 2 + 1] + bv;
                    *reinterpret_cast<float2*>(&oF[(size_t)m * HW + n0]) =
                        make_float2(v0, v1);
                    if (PLANES) {
                        __half2 hv = __floats2half2_rn(v0, v1);
                        *reinterpret_cast<__half2*>(&oP[(size_t)m * HW + n0]) = hv;
                    }
                }
            }
        }
    }
}

// ---------------- fused prep: 5 weight prepacks + x->fp16 convert -----------
__device__ __forceinline__ void prep_one(const float* W, int Kd, int Mvalid,
                                         int Mpad, int Kpad, __half* dst, int idx)
{
    int k = idx / Mpad, m = idx % Mpad;
    float v = (k < Kd && m < Mvalid) ? W[(size_t)m * Kd + k] : 0.f;
    __half h = __float2half_rn(v);
    __half l = __float2half_rn(v - __half2float(h));
    dst[idx] = h;
    dst[(size_t)Kpad * Mpad + idx] = l;
}

constexpr int N_R = 192 * 192;
constexpr int N_O = 192 * 384;
constexpr int N_W = 1632 * 192;
constexpr int N_E = 192 * 192;
constexpr int N_X = (B * CIN * HW) / 2;   // half2 pairs
constexpr int PREP_TOTAL = N_R + N_O + 2 * N_W + N_E + N_X;

__global__ void prep_kernel(const float* __restrict__ w_reduce,
                            const float* __restrict__ w_offset,
                            const float* __restrict__ w_dcnw,
                            const float* __restrict__ w_dcnh,
                            const float* __restrict__ w_expand,
                            const float* __restrict__ x,
                            __half* __restrict__ wpR, __half* __restrict__ wpO,
                            __half* __restrict__ wpW, __half* __restrict__ wpH,
                            __half* __restrict__ wpE, __half* __restrict__ xp)
{
    int idx = blockIdx.x * blockDim.x + threadIdx.x;
    if (idx >= PREP_TOTAL) return;
    if (idx < N_R) { prep_one(w_reduce, 192, 180, 192, 192, wpR, idx); return; }
    idx -= N_R;
    if (idx < N_O) { prep_one(w_offset, 180, 360, 384, 192, wpO, idx); return; }
    idx -= N_O;
    if (idx < N_W) { prep_one(w_dcnw, 1620, 180, 192, 1632, wpW, idx); return; }
    idx -= N_W;
    if (idx < N_W) { prep_one(w_dcnh, 1620, 180, 192, 1632, wpH, idx); return; }
    idx -= N_W;
    if (idx < N_E) { prep_one(w_expand, 180, 192, 192, 192, wpE, idx); return; }
    idx -= N_E;
    // x convert (vectorized by 2)
    float2 v = reinterpret_cast<const float2*>(x)[idx];
    reinterpret_cast<__half2*>(xp)[idx] = __floats2half2_rn(v.x, v.y);
}

// ---------------- deformable im2col -> fp16 col planes ----------------
__global__ void __launch_bounds__(256)
im2col_deform_kernel(const float* __restrict__ xr, const float* __restrict__ offs,
                     __half* __restrict__ cw, __half* __restrict__ ch)
{
    const int b = blockIdx.z;
    const int g = blockIdx.y;
    const int p = blockIdx.x * blockDim.x + threadIdx.x;
    if (p >= HW) return;
    const int h = p / Ww, w = p % Ww;

    const float* xb = xr + (size_t)b * FSTR + (size_t)(g * CG) * HW;

#pragma unroll
    for (int conv = 0; conv < 2; conv++) {
        const float* offb = offs + (size_t)b * OSTR + (size_t)(conv ? CMID : 0) * HW;
        __half* colb = (conv ? ch : cw) + (size_t)b * CSTR
                       + (size_t)(g * CG) * KK * HW + p;

#pragma unroll
        for (int kk = 0; kk < KK; kk++) {
            float oy = offb[(size_t)(g * 18 + kk * 2 + 0) * HW + p];
            float ox = offb[(size_t)(g * 18 + kk * 2 + 1) * HW + p];
            float sy = oy + (float)(kk / 3 - 1 + h);
            float sx = ox + (float)(kk % 3 - 1 + w);
            float y0f = floorf(sy), x0f = floorf(sx);
            float dy = sy - y0f, dx = sx - x0f;
            int y0 = (int)y0f, x0 = (int)x0f;
            int y1 = y0 + 1, x1 = x0 + 1;
            bool vy0 = (y0 >= 0) & (y0 < Hh);
            bool vy1 = (y1 >= 0) & (y1 < Hh);
            bool vx0 = (x0 >= 0) & (x0 < Ww);
            bool vx1 = (x1 >= 0) & (x1 < Ww);
            int y0c = min(max(y0, 0), Hh - 1);
            int y1c = min(max(y1, 0), Hh - 1);
            int x0c = min(max(x0, 0), Ww - 1);
            int x1c = min(max(x1, 0), Ww - 1);
            float w00 = (1.f - dy) * (1.f - dx) * (float)(vy0 && vx0);
            float w01 = (1.f - dy) * dx        * (float)(vy0 && vx1);
            float w10 = dy * (1.f - dx)        * (float)(vy1 && vx0);
            float w11 = dy * dx                * (float)(vy1 && vx1);
            int i00 = y0c * Ww + x0c, i01 = y0c * Ww + x1c;
            int i10 = y1c * Ww + x0c, i11 = y1c * Ww + x1c;

#pragma unroll
            for (int c = 0; c < CG; c++) {
                const float* xc = xb + (size_t)c * HW;
                float v = w00 * xc[i00] + w01 * xc[i01]
                        + w10 * xc[i10] + w11 * xc[i11];
                colb[(size_t)(c * KK + kk) * HW] = __float2half_rn(v);
            }
        }
    }
}

// ---------------- mean over HW of (fw+fh) per (b,c) ----------------
__global__ void reduce_mean_kernel(const float* __restrict__ fw,
                                   const float* __restrict__ fh,
                                   float* __restrict__ avg)
{
    const int bc = blockIdx.x;
    const int bb = bc / CMID, cc = bc % CMID;
    const float* a = fw + (size_t)bb * FSTR + (size_t)cc * HW;
    const float* b = fh + (size_t)bb * FSTR + (size_t)cc * HW;
    float s = 0.f;
    for (int i = threadIdx.x; i < HW; i += 256) s += a[i] + b[i];
    __shared__ float sm[256];
    sm[threadIdx.x] = s;
    __syncthreads();
    for (int st = 128; st > 0; st >>= 1) {
        if (threadIdx.x < st) sm[threadIdx.x] += sm[threadIdx.x + st];
        __syncthreads();
    }
    if (threadIdx.x == 0) avg[bc] = sm[0] * (1.0f / HW);
}

// ---------------- attention softmax ----------------
__global__ void attn_kernel(const float* __restrict__ avg,
                            const float* __restrict__ w_attn,
                            const float* __restrict__ b_attn,
                            float* __restrict__ attn)
{
    const int t = threadIdx.x;
    __shared__ float logits[4];
    if (t < 4) {
        int b = t >> 1, o = t & 1;
        float s = b_attn[o];
        for (int c = 0; c < CMID; c++)
            s += avg[b * CMID + c] * w_attn[o * CMID + c];
        logits[t] = s;
    }
    __syncthreads();
    if (t < 2) {
        float l0 = logits[t * 2 + 0], l1 = logits[t * 2 + 1];
        float m = fmaxf(l0, l1);
        float e0 = expf(l0 - m), e1 = expf(l1 - m);
        float inv = 1.f / (e0 + e1);
        attn[t * 2 + 0] = e0 * inv;   // f_h weight
        attn[t * 2 + 1] = e1 * inv;   // f_w weight
    }
}

// ---------------- launcher ----------------
extern "C" void kernel_launch(void* const* d_in, const int* in_sizes, int n_in,
                              void* d_out, int out_size)
{
    const float* x        = (const float*)d_in[0];
    const float* w_reduce = (const float*)d_in[1];
    const float* b_reduce = (const float*)d_in[2];
    const float* w_offset = (const float*)d_in[3];
    const float* b_offset = (const float*)d_in[4];
    const float* w_dcnw   = (const float*)d_in[5];
    const float* b_dcnw   = (const float*)d_in[6];
    const float* w_dcnh   = (const float*)d_in[7];
    const float* b_dcnh   = (const float*)d_in[8];
    const float* w_expand = (const float*)d_in[9];
    const float* b_expand = (const float*)d_in[10];
    const float* w_attn   = (const float*)d_in[11];
    const float* b_attn   = (const float*)d_in[12];
    float* out = (float*)d_out;

    float *xr, *offs, *fw, *fh, *avg, *attn;
    cudaGetSymbolAddress((void**)&xr,   g_xr);
    cudaGetSymbolAddress((void**)&offs, g_offs);
    cudaGetSymbolAddress((void**)&fw,   g_fw);
    cudaGetSymbolAddress((void**)&fh,   g_fh);
    cudaGetSymbolAddress((void**)&avg,  g_avg);
    cudaGetSymbolAddress((void**)&attn, g_attn);
    __half *xp, *xrp, *cw, *ch, *wpR, *wpO, *wpW, *wpH, *wpE;
    cudaGetSymbolAddress((void**)&xp,  g_xp);
    cudaGetSymbolAddress((void**)&xrp, g_xrp);
    cudaGetSymbolAddress((void**)&cw,  g_cw);
    cudaGetSymbolAddress((void**)&ch,  g_ch);
    cudaGetSymbolAddress((void**)&wpR, g_wpR);
    cudaGetSymbolAddress((void**)&wpO, g_wpO);
    cudaGetSymbolAddress((void**)&wpW, g_wpW);
    cudaGetSymbolAddress((void**)&wpH, g_wpH);
    cudaGetSymbolAddress((void**)&wpE, g_wpE);

    constexpr int SM2 = 2 * 2 * 12800 + 2 * 8704;   // PASSES=2: 68608
    constexpr int SM1 = 2 * 1 * 12800 + 2 * 8704;   // PASSES=1: 43008
    cudaFuncSetAttribute(tgemm_kernel<2, true,  false>,
                         cudaFuncAttributeMaxDynamicSharedMemorySize, SM2);
    cudaFuncSetAttribute(tgemm_kernel<1, false, false>,
                         cudaFuncAttributeMaxDynamicSharedMemorySize, SM1);
    cudaFuncSetAttribute(tgemm_kernel<2, false, true>,
                         cudaFuncAttributeMaxDynamicSharedMemorySize, SM2);

    // 1) fused prep: weight prepacks + x->fp16
    prep_kernel<<<(PREP_TOTAL + 255) / 256, 256>>>(
        w_reduce, w_offset, w_dcnw, w_dcnh, w_expand, x,
        wpR, wpO, wpW, wpH, wpE, xp);

    // 2) xr = reduce(x): M=180(pad192), K=192, 2-pass; emits xr f32 + fp16 plane
    tgemm_kernel<2, true, false><<<dim3(72, 1, B), 256, SM2>>>(
        xp, (size_t)192 * HW, nullptr, nullptr, nullptr,
        wpR, 6, b_reduce, 180, xr, FSTR, xrp, FSTR);

    // 3) offs = offset(xr): M=360(pad384), K=180(pad192), 1-pass
    tgemm_kernel<1, false, false><<<dim3(72, 2, B), 256, SM1>>>(
        xrp, FSTR, nullptr, nullptr, nullptr,
        wpO, 6, b_offset, 360, offs, OSTR, nullptr, 0);

    // 4) im2col -> fp16 col planes (both convs)
    im2col_deform_kernel<<<dim3(HW / 256, G, B), 256>>>(xr, offs, cw, ch);

    // 5) deform GEMMs: M=180(pad192), K=1620(pad1632), 1-pass
    tgemm_kernel<1, false, false><<<dim3(72, 1, B), 256, SM1>>>(
        cw, CSTR, nullptr, nullptr, nullptr,
        wpW, 51, b_dcnw, 180, fw, FSTR, nullptr, 0);
    tgemm_kernel<1, false, false><<<dim3(72, 1, B), 256, SM1>>>(
        ch, CSTR, nullptr, nullptr, nullptr,
        wpH, 51, b_dcnh, 180, fh, FSTR, nullptr, 0);

    // 6) attention
    reduce_mean_kernel<<<B * CMID, 256>>>(fw, fh, avg);
    attn_kernel<<<1, 64>>>(avg, w_attn, b_attn, attn);

    // 7) out = expand(attn0*f_h + attn1*f_w): 2-pass, mix fused into B-loader
    tgemm_kernel<2, false, true><<<dim3(72, 1, B), 256, SM2>>>(
        nullptr, FSTR, fh, fw, attn,
        wpE, 6, b_expand, 192, out, (size_t)CIN * HW, nullptr, 0);
}